// round 11
// baseline (speedup 1.0000x reference)
#include <cuda_runtime.h>
#include <cuda_fp16.h>
#include <math.h>
#include <stdint.h>

// ===========================================================================
// BarrierNet on GB300 (generic compute_103 PTX -> legacy HMMA, rt~16/SMSP):
//   prep  : fused { h1=relu(x@W1+b1)->fp16 A ; [W21|W22]^T->fp16 B ;
//                   zero headAcc + tile counters }
//   gemm2 : mma.sync fp16 GEMM, 128x128 CTA tile, 2 CTA/SM, 3-stage cp.async,
//           head dots in epilogue (atomicAdd), then per-m-tile completion
//           counter: the 8th/last CTA of each m-tile runs the 128-row QP
//           inline (256 thr = 128 rows x 2 lanes) -- overlaps QP (fma pipe)
//           with remaining GEMM CTAs (tensor pipe). No separate qp kernel.
// ===========================================================================

#define BMAX 8192

__device__ __align__(16) __half g_A[(size_t)BMAX * 1024];
__device__ __align__(16) __half g_B[1024 * 1024];   // [n][k]
__device__ float g_headAcc[(size_t)BMAX * 4];
__device__ unsigned int g_cnt[BMAX / 128];

// ---------------------------------------------------------------------------
__device__ __forceinline__ uint32_t smem_u32(const void* p) {
    uint32_t a;
    asm("{ .reg .u64 t; cvta.to.shared.u64 t, %1; cvt.u32.u64 %0, t; }" : "=r"(a) : "l"(p));
    return a;
}
__device__ __forceinline__ void cpasync16(uint32_t s, const void* g) {
    asm volatile("cp.async.cg.shared.global [%0], [%1], 16;" :: "r"(s), "l"(g));
}
#define CP_COMMIT() asm volatile("cp.async.commit_group;" ::: "memory")
#define CP_WAIT1()  asm volatile("cp.async.wait_group 1;" ::: "memory")

__device__ __forceinline__ void ldsm_x4(uint32_t* r, uint32_t addr) {
    asm volatile("ldmatrix.sync.aligned.m8n8.x4.shared.b16 {%0,%1,%2,%3}, [%4];"
                 : "=r"(r[0]), "=r"(r[1]), "=r"(r[2]), "=r"(r[3]) : "r"(addr));
}
__device__ __forceinline__ void mma_f16(float* d, const uint32_t* a, const uint32_t* b) {
    asm volatile(
        "mma.sync.aligned.m16n8k16.row.col.f32.f16.f16.f32 "
        "{%0,%1,%2,%3}, {%4,%5,%6,%7}, {%8,%9}, {%0,%1,%2,%3};"
        : "+f"(d[0]), "+f"(d[1]), "+f"(d[2]), "+f"(d[3])
        : "r"(a[0]), "r"(a[1]), "r"(a[2]), "r"(a[3]), "r"(b[0]), "r"(b[1]));
}

// ---------------------------------------------------------------------------
// Kernel 1 (fused prep): blocks [0, nb1) gemm1 (16 rows each, direct W1 loads);
// blocks [nb1, nb1+1024) wconv transpose+fp16. Block 0 also zeros counters.
// ---------------------------------------------------------------------------
__global__ __launch_bounds__(256)
void prep_kernel(const float* __restrict__ x,
                 const float* __restrict__ W1,
                 const float* __restrict__ b1,
                 const float* __restrict__ W21,
                 const float* __restrict__ W22,
                 int B, int nb1)
{
    __shared__ float sh[33 * 32 + 64];
    const int tid = threadIdx.x;

    if ((int)blockIdx.x < nb1) {
        float* xs = sh;                      // [16][8]
        const int r0 = blockIdx.x * 16;

        if (tid < 128) xs[tid] = x[(size_t)r0 * 8 + tid];
        if (tid < 64)  g_headAcc[(size_t)r0 * 4 + tid] = 0.0f;
        if (blockIdx.x == 0 && tid >= 128 && tid < 128 + BMAX / 128)
            g_cnt[tid - 128] = 0u;

        const float2* __restrict__ W1v = (const float2*)W1;
        const float2* __restrict__ b1v = (const float2*)b1;
        float2 w01[8], w23[8];
        #pragma unroll
        for (int k = 0; k < 8; ++k) {
            w01[k] = W1v[k * 512 + tid];
            w23[k] = W1v[k * 512 + 256 + tid];
        }
        const float2 bb01 = b1v[tid];
        const float2 bb23 = b1v[256 + tid];
        __syncthreads();

        const int c0 = 2 * tid;
        const int c2 = 2 * tid + 512;
        #pragma unroll 4
        for (int r = 0; r < 16; ++r) {
            float xr[8];
            #pragma unroll
            for (int k = 0; k < 8; ++k) xr[k] = xs[r * 8 + k];
            float a0 = bb01.x, a1 = bb01.y, a2 = bb23.x, a3 = bb23.y;
            #pragma unroll
            for (int k = 0; k < 8; ++k) {
                a0 = fmaf(xr[k], w01[k].x, a0);
                a1 = fmaf(xr[k], w01[k].y, a1);
                a2 = fmaf(xr[k], w23[k].x, a2);
                a3 = fmaf(xr[k], w23[k].y, a3);
            }
            __half2 h01 = __floats2half2_rn(fmaxf(a0, 0.f), fmaxf(a1, 0.f));
            __half2 h23 = __floats2half2_rn(fmaxf(a2, 0.f), fmaxf(a3, 0.f));
            *(__half2*)&g_A[(size_t)(r0 + r) * 1024 + c0] = h01;
            *(__half2*)&g_A[(size_t)(r0 + r) * 1024 + c2] = h23;
        }
    } else {
        const int wc = blockIdx.x - nb1;
        const int z  = wc >> 9;
        const int r  = wc & 511;
        const int n0 = (r & 15) * 32;
        const int k0 = (r >> 4) * 32;
        const int tx = tid & 31, ty = tid >> 5;
        float (*tile)[33] = (float (*)[33])sh;
        const float* W = z ? W22 : W21;

        #pragma unroll
        for (int i = ty; i < 32; i += 8)
            tile[i][tx] = W[(size_t)(k0 + i) * 512 + n0 + tx];
        __syncthreads();
        const int zb = z * 512;
        #pragma unroll
        for (int i = ty; i < 32; i += 8)
            g_B[(size_t)(zb + n0 + i) * 1024 + k0 + tx] = __float2half(tile[tx][i]);
    }
}

// ---------------------------------------------------------------------------
// Kernel 2: fp16 GEMM + fused QP tail.
// ---------------------------------------------------------------------------
#define PITCHB   80u
#define OFF_A    0u
#define OFF_B    (128u * PITCHB)            // 10240
#define STAGE_BYTES (2u * 128u * PITCHB)    // 20480
#define SMEM_DYN (3u * STAGE_BYTES)         // 61440

__global__ __launch_bounds__(256, 2)
void gemm2_kernel(const float* __restrict__ b21, const float* __restrict__ b22,
                  const float* __restrict__ W31, const float* __restrict__ W32,
                  const float* __restrict__ x,
                  const float* __restrict__ mean,
                  const float* __restrict__ stdv,
                  const float* __restrict__ obstacles,
                  const float* __restrict__ b31,
                  const float* __restrict__ b32,
                  float* __restrict__ out, int B)
{
    extern __shared__ char smem[];
    __shared__ float sBias[128];
    __shared__ float sWh[256];
    __shared__ unsigned int sDone;

    const uint32_t sb = smem_u32(smem);
    const int tid  = threadIdx.x;
    const int lane = tid & 31;
    const int wid  = tid >> 5;
    const int wm   = wid & 1;
    const int wn   = wid >> 1;
    const int m0   = blockIdx.y * 128;
    const int n0   = blockIdx.x * 128;
    const int half = (n0 >= 512);
    const int nloc = n0 - half * 512;

    if (tid < 128) {
        const float* bp = half ? b22 : b21;
        const float* wp = half ? W32 : W31;
        sBias[tid]       = bp[nloc + tid];
        sWh[2 * tid]     = wp[(nloc + tid) * 2];
        sWh[2 * tid + 1] = wp[(nloc + tid) * 2 + 1];
    }

    const __half* __restrict__ srcA = g_A + (size_t)m0 * 1024;
    const __half* __restrict__ srcB = g_B + (size_t)n0 * 1024;

    const int lrow = tid >> 2;
    const int c8   = (tid & 3) * 8;
    const uint32_t cB = (uint32_t)(tid & 3) * 16u;

    const uint32_t aRC = (uint32_t)(wm * 64 + (lane & 15)) * PITCHB + (uint32_t)(lane >> 4) * 16u;
    const uint32_t bRC = (uint32_t)(wn * 32 + (lane & 7) + ((lane >> 4) << 3)) * PITCHB
                       + (uint32_t)((lane >> 3) & 1) * 16u;

    float acc[4][4][4];
    #pragma unroll
    for (int mb = 0; mb < 4; ++mb)
        #pragma unroll
        for (int nb = 0; nb < 4; ++nb)
            #pragma unroll
            for (int r = 0; r < 4; ++r) acc[mb][nb][r] = 0.0f;

    #define LOAD_STAGE(sbase, k0)                                                   \
    do {                                                                            \
        _Pragma("unroll")                                                           \
        for (int j = 0; j < 2; ++j) {                                               \
            const int r = lrow + j * 64;                                            \
            cpasync16((sbase) + OFF_A + (uint32_t)r * PITCHB + cB,                  \
                      srcA + (size_t)r * 1024 + (k0) + c8);                         \
            cpasync16((sbase) + OFF_B + (uint32_t)r * PITCHB + cB,                  \
                      srcB + (size_t)r * 1024 + (k0) + c8);                         \
        }                                                                           \
    } while (0)

    LOAD_STAGE(sb, 0);
    CP_COMMIT();
    LOAD_STAGE(sb + STAGE_BYTES, 32);
    CP_COMMIT();

    int cur = 0, nxt2 = 2;
    for (int t = 0; t < 32; ++t) {
        CP_WAIT1();
        __syncthreads();

        const uint32_t s = sb + (uint32_t)cur * STAGE_BYTES;
        #pragma unroll
        for (int ks = 0; ks < 2; ++ks) {
            const uint32_t kb = (uint32_t)ks * 32u;
            uint32_t bregs[4][2];
            #pragma unroll
            for (int nbp = 0; nbp < 2; ++nbp) {
                uint32_t r4[4];
                ldsm_x4(r4, s + OFF_B + bRC + (uint32_t)nbp * (16u * PITCHB) + kb);
                bregs[2 * nbp][0] = r4[0]; bregs[2 * nbp][1] = r4[1];
                bregs[2 * nbp + 1][0] = r4[2]; bregs[2 * nbp + 1][1] = r4[3];
            }
            #pragma unroll
            for (int mb = 0; mb < 4; ++mb) {
                uint32_t a4[4];
                ldsm_x4(a4, s + OFF_A + aRC + (uint32_t)mb * (16u * PITCHB) + kb);
                #pragma unroll
                for (int nb = 0; nb < 4; ++nb)
                    mma_f16(acc[mb][nb], a4, bregs[nb]);
            }
        }

        if (t + 2 < 32)
            LOAD_STAGE(sb + (uint32_t)nxt2 * STAGE_BYTES, (t + 2) * 32);
        CP_COMMIT();
        cur  = (cur  == 2) ? 0 : cur  + 1;
        nxt2 = (nxt2 == 2) ? 0 : nxt2 + 1;
    }

    // ---- epilogue: bias+relu, head dots, quad reduce, atomicAdd ----
    const int colBase = wn * 32;
    #pragma unroll
    for (int mb = 0; mb < 4; ++mb) {
        #pragma unroll
        for (int h = 0; h < 2; ++h) {
            float s0 = 0.f, s1 = 0.f;
            #pragma unroll
            for (int nb = 0; nb < 4; ++nb) {
                const int c = colBase + nb * 8 + 2 * (lane & 3);
                const float v0 = fmaxf(acc[mb][nb][h * 2 + 0] + sBias[c],     0.f);
                const float v1 = fmaxf(acc[mb][nb][h * 2 + 1] + sBias[c + 1], 0.f);
                s0 = fmaf(v0, sWh[2 * c],     fmaf(v1, sWh[2 * (c + 1)],     s0));
                s1 = fmaf(v0, sWh[2 * c + 1], fmaf(v1, sWh[2 * (c + 1) + 1], s1));
            }
            s0 += __shfl_xor_sync(0xffffffffu, s0, 1);
            s0 += __shfl_xor_sync(0xffffffffu, s0, 2);
            s1 += __shfl_xor_sync(0xffffffffu, s1, 1);
            s1 += __shfl_xor_sync(0xffffffffu, s1, 2);
            if ((lane & 3) == 0) {
                const int row = m0 + wm * 64 + mb * 16 + h * 8 + (lane >> 2);
                float* dst = g_headAcc + (size_t)row * 4 + half * 2;
                atomicAdd(dst,     s0);
                atomicAdd(dst + 1, s1);
            }
        }
    }

    // ---- completion counter: last of 8 CTAs for this m-tile runs the QP ----
    __threadfence();
    __syncthreads();
    if (tid == 0)
        sDone = atomicAdd(&g_cnt[blockIdx.y], 1u);
    __syncthreads();
    if (sDone != 7u) return;
    __threadfence();

    // ---- fused QP: 256 threads = 128 rows x 2 lanes ----
    {
        const int rowL = tid >> 1;          // 0..127
        const int par  = tid & 1;           // 0: m 0..4, 1: m 5..8
        const int row  = m0 + rowL;
        const bool live = row < B;
        const int rr = live ? row : 0;

        float x0[6];
        #pragma unroll
        for (int i = 0; i < 6; ++i)
            x0[i] = fmaf(__ldg(&x[(size_t)rr * 8 + i]), __ldg(&stdv[i]), __ldg(&mean[i]));

        const float px = x0[0], py = x0[1], theta = x0[2], v = x0[3];
        float st, ct;
        sincosf(theta, &st, &ct);

        const float p0  = __ldcg(&g_headAcc[(size_t)rr * 4 + 0]) + __ldg(&b31[0]);
        const float p1  = __ldcg(&g_headAcc[(size_t)rr * 4 + 1]) + __ldg(&b31[1]);
        const float pp1 = 4.0f / (1.0f + expf(-(__ldcg(&g_headAcc[(size_t)rr * 4 + 2]) + __ldg(&b32[0]))));
        const float pp2 = 4.0f / (1.0f + expf(-(__ldcg(&g_headAcc[(size_t)rr * 4 + 3]) + __ldg(&b32[1]))));

        const float twovv = 2.0f * v * v;
        const float psum  = pp1 + pp2;
        const float pprod = pp1 * pp2;

        float g1[5], g2[5], q[5];
        #pragma unroll
        for (int i = 0; i < 5; ++i) {
            const int m = par * 5 + i;
            if (m < 9) {
                float ox, oy, orad;
                if (m < 8) {
                    ox = __ldg(&obstacles[m * 3]);
                    oy = __ldg(&obstacles[m * 3 + 1]);
                    orad = __ldg(&obstacles[m * 3 + 2]);
                } else { ox = x0[4]; oy = x0[5]; orad = 0.5f; }
                const float dx = px - ox, dy = py - oy;
                const float R  = orad + 0.6f;
                const float barrier = dx * dx + dy * dy - R * R;
                const float proj = dx * ct + dy * st;
                const float bdot = 2.0f * v * proj;
                g1[i] = 2.0f * v * (dx * st - dy * ct);
                g2[i] = -2.0f * proj;
                const float hm = twovv + psum * bdot + pprod * barrier;
                q[i] = fmaf(g1[i], p0, fmaf(g2[i], p1, hm));
            } else {
                g1[i] = 0.f; g2[i] = 0.f; q[i] = 0.f;
            }
        }

        float a = 0.f, bq = 0.f, c = 0.f;
        #pragma unroll
        for (int i = 0; i < 5; ++i) {
            a  = fmaf(g1[i], g1[i], a);
            bq = fmaf(g2[i], g2[i], bq);
            c  = fmaf(g1[i], g2[i], c);
        }
        a  += __shfl_xor_sync(0xffffffffu, a,  1);
        bq += __shfl_xor_sync(0xffffffffu, bq, 1);
        c  += __shfl_xor_sync(0xffffffffu, c,  1);
        const float L = sqrtf(a * a + 2.0f * c * c + bq * bq) + 1e-6f;
        const float alpha = 1.0f / L;

        float lam[5];
        #pragma unroll
        for (int i = 0; i < 5; ++i) lam[i] = 0.0f;

        for (int it = 0; it < 300; ++it) {
            float t1p = ((g1[0] * lam[0] + g1[1] * lam[1]) +
                         (g1[2] * lam[2] + g1[3] * lam[3])) + g1[4] * lam[4];
            float t2p = ((g2[0] * lam[0] + g2[1] * lam[1]) +
                         (g2[2] * lam[2] + g2[3] * lam[3])) + g2[4] * lam[4];
            const float t1 = t1p + __shfl_xor_sync(0xffffffffu, t1p, 1);
            const float t2 = t2p + __shfl_xor_sync(0xffffffffu, t2p, 1);
            #pragma unroll
            for (int i = 0; i < 5; ++i) {
                const float grad = fmaf(g1[i], t1, fmaf(g2[i], t2, q[i]));
                lam[i] = fmaxf(fmaf(-alpha, grad, lam[i]), 0.0f);
            }
        }

        float t1p = 0.f, t2p = 0.f;
        #pragma unroll
        for (int i = 0; i < 5; ++i) {
            t1p = fmaf(g1[i], lam[i], t1p);
            t2p = fmaf(g2[i], lam[i], t2p);
        }
        const float t1 = t1p + __shfl_xor_sync(0xffffffffu, t1p, 1);
        const float t2 = t2p + __shfl_xor_sync(0xffffffffu, t2p, 1);
        if (par == 0 && live) {
            out[(size_t)row * 2 + 0] = -p0 - t1;
            out[(size_t)row * 2 + 1] = -p1 - t2;
        }
    }
}

// ---------------------------------------------------------------------------
extern "C" void kernel_launch(void* const* d_in, const int* in_sizes, int n_in,
                              void* d_out, int out_size)
{
    const float* x    = (const float*)d_in[0];
    const float* mean = (const float*)d_in[1];
    const float* stdv = (const float*)d_in[2];
    const float* W1   = (const float*)d_in[3];
    const float* b1   = (const float*)d_in[4];
    const float* W21  = (const float*)d_in[5];
    const float* b21  = (const float*)d_in[6];
    const float* W22  = (const float*)d_in[7];
    const float* b22  = (const float*)d_in[8];
    const float* W31  = (const float*)d_in[11];
    const float* b31  = (const float*)d_in[12];
    const float* W32  = (const float*)d_in[13];
    const float* b32  = (const float*)d_in[14];
    const float* obstacles = (const float*)d_in[17];
    float* out = (float*)d_out;

    int B = in_sizes[0] / 8;
    if (B > BMAX) B = BMAX;

    cudaFuncSetAttribute(gemm2_kernel,
                         cudaFuncAttributeMaxDynamicSharedMemorySize, SMEM_DYN);

    const int nb1 = (B + 15) / 16;
    prep_kernel<<<nb1 + 1024, 256>>>(x, W1, b1, W21, W22, B, nb1);

    dim3 g2(8, (B + 127) / 128);
    gemm2_kernel<<<g2, 256, SMEM_DYN>>>(b21, b22, W31, W32,
                                        x, mean, stdv, obstacles, b31, b32,
                                        out, B);
}

// round 12
// speedup vs baseline: 1.0792x; 1.0792x over previous
#include <cuda_runtime.h>
#include <cuda_fp16.h>
#include <math.h>
#include <stdint.h>

// ===========================================================================
// BarrierNet on GB300 (generic compute_103 PTX -> legacy HMMA):
//   prep  : fused { h1=relu(x@W1+b1)->fp16 A ; [W21|W22]^T->fp16 B ; zero acc }
//   gemm2 : mma.sync fp16 GEMM with FP16 ACCUMULATORS promoted to fp32 every
//           k32 stage (gamble: f16-acc HMMA at 2x rate of f32-acc),
//           128x128 CTA tile, 2 CTA/SM, 3-stage cp.async, fused head dots
//   qp    : rank-2 dual PGA, 2 lanes per row, 300 iters (separate kernel --
//           R11 fusion regressed via register pressure)
// ===========================================================================

#define BMAX 8192

__device__ __align__(16) __half g_A[(size_t)BMAX * 1024];
__device__ __align__(16) __half g_B[1024 * 1024];   // [n][k]
__device__ float g_headAcc[(size_t)BMAX * 4];

// ---------------------------------------------------------------------------
__device__ __forceinline__ uint32_t smem_u32(const void* p) {
    uint32_t a;
    asm("{ .reg .u64 t; cvta.to.shared.u64 t, %1; cvt.u32.u64 %0, t; }" : "=r"(a) : "l"(p));
    return a;
}
__device__ __forceinline__ void cpasync16(uint32_t s, const void* g) {
    asm volatile("cp.async.cg.shared.global [%0], [%1], 16;" :: "r"(s), "l"(g));
}
#define CP_COMMIT() asm volatile("cp.async.commit_group;" ::: "memory")
#define CP_WAIT1()  asm volatile("cp.async.wait_group 1;" ::: "memory")

__device__ __forceinline__ void ldsm_x4(uint32_t* r, uint32_t addr) {
    asm volatile("ldmatrix.sync.aligned.m8n8.x4.shared.b16 {%0,%1,%2,%3}, [%4];"
                 : "=r"(r[0]), "=r"(r[1]), "=r"(r[2]), "=r"(r[3]) : "r"(addr));
}
// fp16-accumulator HMMA: D,C are 2x .f16x2 regs
__device__ __forceinline__ void mma_f16acc(uint32_t* d, const uint32_t* a, const uint32_t* b) {
    asm volatile(
        "mma.sync.aligned.m16n8k16.row.col.f16.f16.f16.f16 "
        "{%0,%1}, {%2,%3,%4,%5}, {%6,%7}, {%0,%1};"
        : "+r"(d[0]), "+r"(d[1])
        : "r"(a[0]), "r"(a[1]), "r"(a[2]), "r"(a[3]), "r"(b[0]), "r"(b[1]));
}

// ---------------------------------------------------------------------------
// Kernel 1 (fused prep): blocks [0, nb1) gemm1 (16 rows each, direct W1 loads);
// blocks [nb1, nb1+1024) wconv transpose+fp16.
// ---------------------------------------------------------------------------
__global__ __launch_bounds__(256)
void prep_kernel(const float* __restrict__ x,
                 const float* __restrict__ W1,
                 const float* __restrict__ b1,
                 const float* __restrict__ W21,
                 const float* __restrict__ W22,
                 int B, int nb1)
{
    __shared__ float sh[33 * 32 + 64];
    const int tid = threadIdx.x;

    if ((int)blockIdx.x < nb1) {
        float* xs = sh;                      // [16][8]
        const int r0 = blockIdx.x * 16;

        if (tid < 128) xs[tid] = x[(size_t)r0 * 8 + tid];
        if (tid < 64)  g_headAcc[(size_t)r0 * 4 + tid] = 0.0f;

        const float2* __restrict__ W1v = (const float2*)W1;
        const float2* __restrict__ b1v = (const float2*)b1;
        float2 w01[8], w23[8];
        #pragma unroll
        for (int k = 0; k < 8; ++k) {
            w01[k] = W1v[k * 512 + tid];
            w23[k] = W1v[k * 512 + 256 + tid];
        }
        const float2 bb01 = b1v[tid];
        const float2 bb23 = b1v[256 + tid];
        __syncthreads();

        const int c0 = 2 * tid;
        const int c2 = 2 * tid + 512;
        #pragma unroll 4
        for (int r = 0; r < 16; ++r) {
            float xr[8];
            #pragma unroll
            for (int k = 0; k < 8; ++k) xr[k] = xs[r * 8 + k];
            float a0 = bb01.x, a1 = bb01.y, a2 = bb23.x, a3 = bb23.y;
            #pragma unroll
            for (int k = 0; k < 8; ++k) {
                a0 = fmaf(xr[k], w01[k].x, a0);
                a1 = fmaf(xr[k], w01[k].y, a1);
                a2 = fmaf(xr[k], w23[k].x, a2);
                a3 = fmaf(xr[k], w23[k].y, a3);
            }
            __half2 h01 = __floats2half2_rn(fmaxf(a0, 0.f), fmaxf(a1, 0.f));
            __half2 h23 = __floats2half2_rn(fmaxf(a2, 0.f), fmaxf(a3, 0.f));
            *(__half2*)&g_A[(size_t)(r0 + r) * 1024 + c0] = h01;
            *(__half2*)&g_A[(size_t)(r0 + r) * 1024 + c2] = h23;
        }
    } else {
        const int wc = blockIdx.x - nb1;
        const int z  = wc >> 9;
        const int r  = wc & 511;
        const int n0 = (r & 15) * 32;
        const int k0 = (r >> 4) * 32;
        const int tx = tid & 31, ty = tid >> 5;
        float (*tile)[33] = (float (*)[33])sh;
        const float* W = z ? W22 : W21;

        #pragma unroll
        for (int i = ty; i < 32; i += 8)
            tile[i][tx] = W[(size_t)(k0 + i) * 512 + n0 + tx];
        __syncthreads();
        const int zb = z * 512;
        #pragma unroll
        for (int i = ty; i < 32; i += 8)
            g_B[(size_t)(zb + n0 + i) * 1024 + k0 + tx] = __float2half(tile[tx][i]);
    }
}

// ---------------------------------------------------------------------------
// Kernel 2: fp16 GEMM (f16 accumulators, promoted to f32 every k32 stage),
// 128(m) x 128(n) CTA tile, 2 CTA/SM, 3-stage pipeline.
// ---------------------------------------------------------------------------
#define PITCHB   80u
#define OFF_A    0u
#define OFF_B    (128u * PITCHB)            // 10240
#define STAGE_BYTES (2u * 128u * PITCHB)    // 20480
#define SMEM_DYN (3u * STAGE_BYTES)         // 61440

__global__ __launch_bounds__(256, 2)
void gemm2_kernel(const float* __restrict__ b21, const float* __restrict__ b22,
                  const float* __restrict__ W31, const float* __restrict__ W32)
{
    extern __shared__ char smem[];
    __shared__ float sBias[128];
    __shared__ float sWh[256];

    const uint32_t sb = smem_u32(smem);
    const int tid  = threadIdx.x;
    const int lane = tid & 31;
    const int wid  = tid >> 5;
    const int wm   = wid & 1;
    const int wn   = wid >> 1;
    const int m0   = blockIdx.y * 128;
    const int n0   = blockIdx.x * 128;
    const int half = (n0 >= 512);
    const int nloc = n0 - half * 512;

    if (tid < 128) {
        const float* bp = half ? b22 : b21;
        const float* wp = half ? W32 : W31;
        sBias[tid]       = bp[nloc + tid];
        sWh[2 * tid]     = wp[(nloc + tid) * 2];
        sWh[2 * tid + 1] = wp[(nloc + tid) * 2 + 1];
    }

    const __half* __restrict__ srcA = g_A + (size_t)m0 * 1024;
    const __half* __restrict__ srcB = g_B + (size_t)n0 * 1024;

    const int lrow = tid >> 2;
    const int c8   = (tid & 3) * 8;
    const uint32_t cB = (uint32_t)(tid & 3) * 16u;

    const uint32_t aRC = (uint32_t)(wm * 64 + (lane & 15)) * PITCHB + (uint32_t)(lane >> 4) * 16u;
    const uint32_t bRC = (uint32_t)(wn * 32 + (lane & 7) + ((lane >> 4) << 3)) * PITCHB
                       + (uint32_t)((lane >> 3) & 1) * 16u;

    float acc[4][4][4];
    #pragma unroll
    for (int mb = 0; mb < 4; ++mb)
        #pragma unroll
        for (int nb = 0; nb < 4; ++nb)
            #pragma unroll
            for (int r = 0; r < 4; ++r) acc[mb][nb][r] = 0.0f;

    #define LOAD_STAGE(sbase, k0)                                                   \
    do {                                                                            \
        _Pragma("unroll")                                                           \
        for (int j = 0; j < 2; ++j) {                                               \
            const int r = lrow + j * 64;                                            \
            cpasync16((sbase) + OFF_A + (uint32_t)r * PITCHB + cB,                  \
                      srcA + (size_t)r * 1024 + (k0) + c8);                         \
            cpasync16((sbase) + OFF_B + (uint32_t)r * PITCHB + cB,                  \
                      srcB + (size_t)r * 1024 + (k0) + c8);                         \
        }                                                                           \
    } while (0)

    LOAD_STAGE(sb, 0);
    CP_COMMIT();
    LOAD_STAGE(sb + STAGE_BYTES, 32);
    CP_COMMIT();

    int cur = 0, nxt2 = 2;
    for (int t = 0; t < 32; ++t) {
        CP_WAIT1();
        __syncthreads();

        // fresh f16 accumulators for this k32 chunk
        uint32_t hacc[4][4][2];
        #pragma unroll
        for (int mb = 0; mb < 4; ++mb)
            #pragma unroll
            for (int nb = 0; nb < 4; ++nb) {
                hacc[mb][nb][0] = 0u;
                hacc[mb][nb][1] = 0u;
            }

        const uint32_t s = sb + (uint32_t)cur * STAGE_BYTES;
        #pragma unroll
        for (int ks = 0; ks < 2; ++ks) {
            const uint32_t kb = (uint32_t)ks * 32u;
            uint32_t bregs[4][2];
            #pragma unroll
            for (int nbp = 0; nbp < 2; ++nbp) {
                uint32_t r4[4];
                ldsm_x4(r4, s + OFF_B + bRC + (uint32_t)nbp * (16u * PITCHB) + kb);
                bregs[2 * nbp][0] = r4[0]; bregs[2 * nbp][1] = r4[1];
                bregs[2 * nbp + 1][0] = r4[2]; bregs[2 * nbp + 1][1] = r4[3];
            }
            #pragma unroll
            for (int mb = 0; mb < 4; ++mb) {
                uint32_t a4[4];
                ldsm_x4(a4, s + OFF_A + aRC + (uint32_t)mb * (16u * PITCHB) + kb);
                #pragma unroll
                for (int nb = 0; nb < 4; ++nb)
                    mma_f16acc(hacc[mb][nb], a4, bregs[nb]);
            }
        }

        // promote chunk sums to fp32
        #pragma unroll
        for (int mb = 0; mb < 4; ++mb)
            #pragma unroll
            for (int nb = 0; nb < 4; ++nb) {
                const float2 f0 = __half22float2(*(__half2*)&hacc[mb][nb][0]);
                const float2 f1 = __half22float2(*(__half2*)&hacc[mb][nb][1]);
                acc[mb][nb][0] += f0.x;
                acc[mb][nb][1] += f0.y;
                acc[mb][nb][2] += f1.x;
                acc[mb][nb][3] += f1.y;
            }

        if (t + 2 < 32)
            LOAD_STAGE(sb + (uint32_t)nxt2 * STAGE_BYTES, (t + 2) * 32);
        CP_COMMIT();
        cur  = (cur  == 2) ? 0 : cur  + 1;
        nxt2 = (nxt2 == 2) ? 0 : nxt2 + 1;
    }

    // epilogue: bias+relu, head dots, quad reduce, atomicAdd
    const int colBase = wn * 32;
    #pragma unroll
    for (int mb = 0; mb < 4; ++mb) {
        #pragma unroll
        for (int h = 0; h < 2; ++h) {
            float s0 = 0.f, s1 = 0.f;
            #pragma unroll
            for (int nb = 0; nb < 4; ++nb) {
                const int c = colBase + nb * 8 + 2 * (lane & 3);
                const float v0 = fmaxf(acc[mb][nb][h * 2 + 0] + sBias[c],     0.f);
                const float v1 = fmaxf(acc[mb][nb][h * 2 + 1] + sBias[c + 1], 0.f);
                s0 = fmaf(v0, sWh[2 * c],     fmaf(v1, sWh[2 * (c + 1)],     s0));
                s1 = fmaf(v0, sWh[2 * c + 1], fmaf(v1, sWh[2 * (c + 1) + 1], s1));
            }
            s0 += __shfl_xor_sync(0xffffffffu, s0, 1);
            s0 += __shfl_xor_sync(0xffffffffu, s0, 2);
            s1 += __shfl_xor_sync(0xffffffffu, s1, 1);
            s1 += __shfl_xor_sync(0xffffffffu, s1, 2);
            if ((lane & 3) == 0) {
                const int row = m0 + wm * 64 + mb * 16 + h * 8 + (lane >> 2);
                float* dst = g_headAcc + (size_t)row * 4 + half * 2;
                atomicAdd(dst,     s0);
                atomicAdd(dst + 1, s1);
            }
        }
    }
}

// ---------------------------------------------------------------------------
// Kernel 3: QP, 2 lanes per row, 64-thread blocks.
// ---------------------------------------------------------------------------
__global__ __launch_bounds__(64)
void qp_kernel(const float* __restrict__ x,
               const float* __restrict__ mean,
               const float* __restrict__ stdv,
               const float* __restrict__ obstacles,
               const float* __restrict__ b31,
               const float* __restrict__ b32,
               float* __restrict__ out, int B)
{
    __shared__ float sObs[24];
    __shared__ float sMean[6], sStd[6], sB[4];
    const int tid = threadIdx.x;
    if (tid < 24) sObs[tid] = obstacles[tid];
    if (tid < 6) { sMean[tid] = mean[tid]; sStd[tid] = stdv[tid]; }
    if (tid < 2) { sB[tid] = b31[tid]; sB[2 + tid] = b32[tid]; }
    __syncthreads();

    const int gt   = blockIdx.x * 64 + tid;
    const int rowR = gt >> 1;
    const int par  = gt & 1;
    const int row  = rowR < B ? rowR : 0;

    float x0[6];
    #pragma unroll
    for (int i = 0; i < 6; ++i)
        x0[i] = fmaf(x[(size_t)row * 8 + i], sStd[i], sMean[i]);

    const float px = x0[0], py = x0[1], theta = x0[2], v = x0[3];
    float st, ct;
    sincosf(theta, &st, &ct);

    const float p0  = g_headAcc[(size_t)row * 4 + 0] + sB[0];
    const float p1  = g_headAcc[(size_t)row * 4 + 1] + sB[1];
    const float pp1 = 4.0f / (1.0f + expf(-(g_headAcc[(size_t)row * 4 + 2] + sB[2])));
    const float pp2 = 4.0f / (1.0f + expf(-(g_headAcc[(size_t)row * 4 + 3] + sB[3])));

    const float twovv = 2.0f * v * v;
    const float psum  = pp1 + pp2;
    const float pprod = pp1 * pp2;

    float g1[5], g2[5], q[5];
    #pragma unroll
    for (int i = 0; i < 5; ++i) {
        const int m = par * 5 + i;
        if (m < 9) {
            float ox, oy, orad;
            if (m < 8) { ox = sObs[m * 3]; oy = sObs[m * 3 + 1]; orad = sObs[m * 3 + 2]; }
            else       { ox = x0[4];       oy = x0[5];           orad = 0.5f; }
            const float dx = px - ox, dy = py - oy;
            const float R  = orad + 0.6f;
            const float barrier = dx * dx + dy * dy - R * R;
            const float proj = dx * ct + dy * st;
            const float bdot = 2.0f * v * proj;
            g1[i] = 2.0f * v * (dx * st - dy * ct);
            g2[i] = -2.0f * proj;
            const float hm = twovv + psum * bdot + pprod * barrier;
            q[i] = fmaf(g1[i], p0, fmaf(g2[i], p1, hm));
        } else {
            g1[i] = 0.f; g2[i] = 0.f; q[i] = 0.f;
        }
    }

    float a = 0.f, bq = 0.f, c = 0.f;
    #pragma unroll
    for (int i = 0; i < 5; ++i) {
        a  = fmaf(g1[i], g1[i], a);
        bq = fmaf(g2[i], g2[i], bq);
        c  = fmaf(g1[i], g2[i], c);
    }
    a  += __shfl_xor_sync(0xffffffffu, a,  1);
    bq += __shfl_xor_sync(0xffffffffu, bq, 1);
    c  += __shfl_xor_sync(0xffffffffu, c,  1);
    const float L = sqrtf(a * a + 2.0f * c * c + bq * bq) + 1e-6f;
    const float alpha = 1.0f / L;

    float lam[5];
    #pragma unroll
    for (int i = 0; i < 5; ++i) lam[i] = 0.0f;

    for (int it = 0; it < 300; ++it) {
        float t1p = ((g1[0] * lam[0] + g1[1] * lam[1]) +
                     (g1[2] * lam[2] + g1[3] * lam[3])) + g1[4] * lam[4];
        float t2p = ((g2[0] * lam[0] + g2[1] * lam[1]) +
                     (g2[2] * lam[2] + g2[3] * lam[3])) + g2[4] * lam[4];
        const float t1 = t1p + __shfl_xor_sync(0xffffffffu, t1p, 1);
        const float t2 = t2p + __shfl_xor_sync(0xffffffffu, t2p, 1);
        #pragma unroll
        for (int i = 0; i < 5; ++i) {
            const float grad = fmaf(g1[i], t1, fmaf(g2[i], t2, q[i]));
            lam[i] = fmaxf(fmaf(-alpha, grad, lam[i]), 0.0f);
        }
    }

    float t1p = 0.f, t2p = 0.f;
    #pragma unroll
    for (int i = 0; i < 5; ++i) {
        t1p = fmaf(g1[i], lam[i], t1p);
        t2p = fmaf(g2[i], lam[i], t2p);
    }
    const float t1 = t1p + __shfl_xor_sync(0xffffffffu, t1p, 1);
    const float t2 = t2p + __shfl_xor_sync(0xffffffffu, t2p, 1);
    if (par == 0 && rowR < B) {
        out[(size_t)rowR * 2 + 0] = -p0 - t1;
        out[(size_t)rowR * 2 + 1] = -p1 - t2;
    }
}

// ---------------------------------------------------------------------------
extern "C" void kernel_launch(void* const* d_in, const int* in_sizes, int n_in,
                              void* d_out, int out_size)
{
    const float* x    = (const float*)d_in[0];
    const float* mean = (const float*)d_in[1];
    const float* stdv = (const float*)d_in[2];
    const float* W1   = (const float*)d_in[3];
    const float* b1   = (const float*)d_in[4];
    const float* W21  = (const float*)d_in[5];
    const float* b21  = (const float*)d_in[6];
    const float* W22  = (const float*)d_in[7];
    const float* b22  = (const float*)d_in[8];
    const float* W31  = (const float*)d_in[11];
    const float* b31  = (const float*)d_in[12];
    const float* W32  = (const float*)d_in[13];
    const float* b32  = (const float*)d_in[14];
    const float* obstacles = (const float*)d_in[17];
    float* out = (float*)d_out;

    int B = in_sizes[0] / 8;
    if (B > BMAX) B = BMAX;

    cudaFuncSetAttribute(gemm2_kernel,
                         cudaFuncAttributeMaxDynamicSharedMemorySize, SMEM_DYN);

    const int nb1 = (B + 15) / 16;
    prep_kernel<<<nb1 + 1024, 256>>>(x, W1, b1, W21, W22, B, nb1);

    dim3 g2(8, (B + 127) / 128);
    gemm2_kernel<<<g2, 256, SMEM_DYN>>>(b21, b22, W31, W32);

    qp_kernel<<<(2 * B + 63) / 64, 64>>>(x, mean, stdv, obstacles, b31, b32, out, B);
}

// round 13
// speedup vs baseline: 1.1195x; 1.0374x over previous
#include <cuda_runtime.h>
#include <cuda_fp16.h>
#include <math.h>
#include <stdint.h>

// ===========================================================================
// BarrierNet on GB300 (generic compute_103 PTX -> legacy HMMA, rt~16/SMSP):
//   prep  : fused { h1=relu(x@W1+b1)->fp16 A ; [W21|W22]^T->fp16 B ;
//                   zero headAcc + m-tile counters }
//   gemm2 : flattened grid = 8*mTiles GEMM blocks + mTiles QP blocks.
//           GEMM blocks: R10 mainloop (f32-acc mma.sync, 128x128, 2 CTA/SM,
//           3-stage cp.async), head-dot epilogue, fence + counter bump.
//           QP blocks: spin on counter (acquire + nanosleep), then 128-row
//           rank-2 dual PGA (2 lanes/row, 300 it). QP overlaps the GEMM tail.
// ===========================================================================

#define BMAX 8192

__device__ __align__(16) __half g_A[(size_t)BMAX * 1024];
__device__ __align__(16) __half g_B[1024 * 1024];   // [n][k]
__device__ float g_headAcc[(size_t)BMAX * 4];
__device__ unsigned int g_cnt[BMAX / 128];

// ---------------------------------------------------------------------------
__device__ __forceinline__ uint32_t smem_u32(const void* p) {
    uint32_t a;
    asm("{ .reg .u64 t; cvta.to.shared.u64 t, %1; cvt.u32.u64 %0, t; }" : "=r"(a) : "l"(p));
    return a;
}
__device__ __forceinline__ void cpasync16(uint32_t s, const void* g) {
    asm volatile("cp.async.cg.shared.global [%0], [%1], 16;" :: "r"(s), "l"(g));
}
#define CP_COMMIT() asm volatile("cp.async.commit_group;" ::: "memory")
#define CP_WAIT1()  asm volatile("cp.async.wait_group 1;" ::: "memory")

__device__ __forceinline__ void ldsm_x4(uint32_t* r, uint32_t addr) {
    asm volatile("ldmatrix.sync.aligned.m8n8.x4.shared.b16 {%0,%1,%2,%3}, [%4];"
                 : "=r"(r[0]), "=r"(r[1]), "=r"(r[2]), "=r"(r[3]) : "r"(addr));
}
__device__ __forceinline__ void mma_f16(float* d, const uint32_t* a, const uint32_t* b) {
    asm volatile(
        "mma.sync.aligned.m16n8k16.row.col.f32.f16.f16.f32 "
        "{%0,%1,%2,%3}, {%4,%5,%6,%7}, {%8,%9}, {%0,%1,%2,%3};"
        : "+f"(d[0]), "+f"(d[1]), "+f"(d[2]), "+f"(d[3])
        : "r"(a[0]), "r"(a[1]), "r"(a[2]), "r"(a[3]), "r"(b[0]), "r"(b[1]));
}

// ---------------------------------------------------------------------------
// Kernel 1 (fused prep): blocks [0, nb1) gemm1 (16 rows each, direct W1 loads);
// blocks [nb1, nb1+1024) wconv transpose+fp16. Block 0 zeroes tile counters.
// ---------------------------------------------------------------------------
__global__ __launch_bounds__(256)
void prep_kernel(const float* __restrict__ x,
                 const float* __restrict__ W1,
                 const float* __restrict__ b1,
                 const float* __restrict__ W21,
                 const float* __restrict__ W22,
                 int B, int nb1)
{
    __shared__ float sh[33 * 32 + 64];
    const int tid = threadIdx.x;

    if ((int)blockIdx.x < nb1) {
        float* xs = sh;                      // [16][8]
        const int r0 = blockIdx.x * 16;

        if (tid < 128) xs[tid] = x[(size_t)r0 * 8 + tid];
        if (tid < 64)  g_headAcc[(size_t)r0 * 4 + tid] = 0.0f;
        if (blockIdx.x == 0 && tid >= 192)
            g_cnt[tid - 192] = 0u;           // 64 m-tile counters

        const float2* __restrict__ W1v = (const float2*)W1;
        const float2* __restrict__ b1v = (const float2*)b1;
        float2 w01[8], w23[8];
        #pragma unroll
        for (int k = 0; k < 8; ++k) {
            w01[k] = W1v[k * 512 + tid];
            w23[k] = W1v[k * 512 + 256 + tid];
        }
        const float2 bb01 = b1v[tid];
        const float2 bb23 = b1v[256 + tid];
        __syncthreads();

        const int c0 = 2 * tid;
        const int c2 = 2 * tid + 512;
        #pragma unroll 4
        for (int r = 0; r < 16; ++r) {
            float xr[8];
            #pragma unroll
            for (int k = 0; k < 8; ++k) xr[k] = xs[r * 8 + k];
            float a0 = bb01.x, a1 = bb01.y, a2 = bb23.x, a3 = bb23.y;
            #pragma unroll
            for (int k = 0; k < 8; ++k) {
                a0 = fmaf(xr[k], w01[k].x, a0);
                a1 = fmaf(xr[k], w01[k].y, a1);
                a2 = fmaf(xr[k], w23[k].x, a2);
                a3 = fmaf(xr[k], w23[k].y, a3);
            }
            __half2 h01 = __floats2half2_rn(fmaxf(a0, 0.f), fmaxf(a1, 0.f));
            __half2 h23 = __floats2half2_rn(fmaxf(a2, 0.f), fmaxf(a3, 0.f));
            *(__half2*)&g_A[(size_t)(r0 + r) * 1024 + c0] = h01;
            *(__half2*)&g_A[(size_t)(r0 + r) * 1024 + c2] = h23;
        }
    } else {
        const int wc = blockIdx.x - nb1;
        const int z  = wc >> 9;
        const int r  = wc & 511;
        const int n0 = (r & 15) * 32;
        const int k0 = (r >> 4) * 32;
        const int tx = tid & 31, ty = tid >> 5;
        float (*tile)[33] = (float (*)[33])sh;
        const float* W = z ? W22 : W21;

        #pragma unroll
        for (int i = ty; i < 32; i += 8)
            tile[i][tx] = W[(size_t)(k0 + i) * 512 + n0 + tx];
        __syncthreads();
        const int zb = z * 512;
        #pragma unroll
        for (int i = ty; i < 32; i += 8)
            g_B[(size_t)(zb + n0 + i) * 1024 + k0 + tx] = __float2half(tile[tx][i]);
    }
}

// ---------------------------------------------------------------------------
// Kernel 2: GEMM blocks [0, 8*mTiles) + QP blocks [8*mTiles, 9*mTiles).
// ---------------------------------------------------------------------------
#define PITCHB   80u
#define OFF_A    0u
#define OFF_B    (128u * PITCHB)            // 10240
#define STAGE_BYTES (2u * 128u * PITCHB)    // 20480
#define SMEM_DYN (3u * STAGE_BYTES)         // 61440

__global__ __launch_bounds__(256, 2)
void gemm2_kernel(const float* __restrict__ b21, const float* __restrict__ b22,
                  const float* __restrict__ W31, const float* __restrict__ W32,
                  const float* __restrict__ x,
                  const float* __restrict__ mean,
                  const float* __restrict__ stdv,
                  const float* __restrict__ obstacles,
                  const float* __restrict__ b31,
                  const float* __restrict__ b32,
                  float* __restrict__ out, int B, int nGemm)
{
    const int tid = threadIdx.x;

    if ((int)blockIdx.x < nGemm) {
        // ================= GEMM path (identical to R10) =================
        extern __shared__ char smem[];
        __shared__ float sBias[128];
        __shared__ float sWh[256];

        const uint32_t sb = smem_u32(smem);
        const int lane = tid & 31;
        const int wid  = tid >> 5;
        const int wm   = wid & 1;
        const int wn   = wid >> 1;
        const int bx   = blockIdx.x & 7;
        const int by   = blockIdx.x >> 3;
        const int m0   = by * 128;
        const int n0   = bx * 128;
        const int half = (n0 >= 512);
        const int nloc = n0 - half * 512;

        if (tid < 128) {
            const float* bp = half ? b22 : b21;
            const float* wp = half ? W32 : W31;
            sBias[tid]       = bp[nloc + tid];
            sWh[2 * tid]     = wp[(nloc + tid) * 2];
            sWh[2 * tid + 1] = wp[(nloc + tid) * 2 + 1];
        }

        const __half* __restrict__ srcA = g_A + (size_t)m0 * 1024;
        const __half* __restrict__ srcB = g_B + (size_t)n0 * 1024;

        const int lrow = tid >> 2;
        const int c8   = (tid & 3) * 8;
        const uint32_t cB = (uint32_t)(tid & 3) * 16u;

        const uint32_t aRC = (uint32_t)(wm * 64 + (lane & 15)) * PITCHB + (uint32_t)(lane >> 4) * 16u;
        const uint32_t bRC = (uint32_t)(wn * 32 + (lane & 7) + ((lane >> 4) << 3)) * PITCHB
                           + (uint32_t)((lane >> 3) & 1) * 16u;

        float acc[4][4][4];
        #pragma unroll
        for (int mb = 0; mb < 4; ++mb)
            #pragma unroll
            for (int nb = 0; nb < 4; ++nb)
                #pragma unroll
                for (int r = 0; r < 4; ++r) acc[mb][nb][r] = 0.0f;

        #define LOAD_STAGE(sbase, k0)                                               \
        do {                                                                        \
            _Pragma("unroll")                                                       \
            for (int j = 0; j < 2; ++j) {                                           \
                const int r = lrow + j * 64;                                        \
                cpasync16((sbase) + OFF_A + (uint32_t)r * PITCHB + cB,              \
                          srcA + (size_t)r * 1024 + (k0) + c8);                     \
                cpasync16((sbase) + OFF_B + (uint32_t)r * PITCHB + cB,              \
                          srcB + (size_t)r * 1024 + (k0) + c8);                     \
            }                                                                       \
        } while (0)

        LOAD_STAGE(sb, 0);
        CP_COMMIT();
        LOAD_STAGE(sb + STAGE_BYTES, 32);
        CP_COMMIT();

        int cur = 0, nxt2 = 2;
        for (int t = 0; t < 32; ++t) {
            CP_WAIT1();
            __syncthreads();

            const uint32_t s = sb + (uint32_t)cur * STAGE_BYTES;
            #pragma unroll
            for (int ks = 0; ks < 2; ++ks) {
                const uint32_t kb = (uint32_t)ks * 32u;
                uint32_t bregs[4][2];
                #pragma unroll
                for (int nbp = 0; nbp < 2; ++nbp) {
                    uint32_t r4[4];
                    ldsm_x4(r4, s + OFF_B + bRC + (uint32_t)nbp * (16u * PITCHB) + kb);
                    bregs[2 * nbp][0] = r4[0]; bregs[2 * nbp][1] = r4[1];
                    bregs[2 * nbp + 1][0] = r4[2]; bregs[2 * nbp + 1][1] = r4[3];
                }
                #pragma unroll
                for (int mb = 0; mb < 4; ++mb) {
                    uint32_t a4[4];
                    ldsm_x4(a4, s + OFF_A + aRC + (uint32_t)mb * (16u * PITCHB) + kb);
                    #pragma unroll
                    for (int nb = 0; nb < 4; ++nb)
                        mma_f16(acc[mb][nb], a4, bregs[nb]);
                }
            }

            if (t + 2 < 32)
                LOAD_STAGE(sb + (uint32_t)nxt2 * STAGE_BYTES, (t + 2) * 32);
            CP_COMMIT();
            cur  = (cur  == 2) ? 0 : cur  + 1;
            nxt2 = (nxt2 == 2) ? 0 : nxt2 + 1;
        }

        // epilogue: bias+relu, head dots, quad reduce, atomicAdd
        const int colBase = wn * 32;
        #pragma unroll
        for (int mb = 0; mb < 4; ++mb) {
            #pragma unroll
            for (int h = 0; h < 2; ++h) {
                float s0 = 0.f, s1 = 0.f;
                #pragma unroll
                for (int nb = 0; nb < 4; ++nb) {
                    const int c = colBase + nb * 8 + 2 * (lane & 3);
                    const float v0 = fmaxf(acc[mb][nb][h * 2 + 0] + sBias[c],     0.f);
                    const float v1 = fmaxf(acc[mb][nb][h * 2 + 1] + sBias[c + 1], 0.f);
                    s0 = fmaf(v0, sWh[2 * c],     fmaf(v1, sWh[2 * (c + 1)],     s0));
                    s1 = fmaf(v0, sWh[2 * c + 1], fmaf(v1, sWh[2 * (c + 1) + 1], s1));
                }
                s0 += __shfl_xor_sync(0xffffffffu, s0, 1);
                s0 += __shfl_xor_sync(0xffffffffu, s0, 2);
                s1 += __shfl_xor_sync(0xffffffffu, s1, 1);
                s1 += __shfl_xor_sync(0xffffffffu, s1, 2);
                if ((lane & 3) == 0) {
                    const int row = m0 + wm * 64 + mb * 16 + h * 8 + (lane >> 2);
                    float* dst = g_headAcc + (size_t)row * 4 + half * 2;
                    atomicAdd(dst,     s0);
                    atomicAdd(dst + 1, s1);
                }
            }
        }

        // publish completion of this n-tile for m-tile `by`
        __threadfence();
        __syncthreads();
        if (tid == 0) atomicAdd(&g_cnt[by], 1u);
    } else {
        // ================= QP path (one block per m-tile) =================
        const int by = (int)blockIdx.x - nGemm;
        const int m0 = by * 128;

        // spin until all 8 GEMM n-tile blocks of this m-tile have published
        if (tid == 0) {
            unsigned int v;
            do {
                asm volatile("ld.acquire.gpu.u32 %0, [%1];" : "=r"(v) : "l"(&g_cnt[by]) : "memory");
                if (v < 8u) __nanosleep(256);
            } while (v < 8u);
        }
        __syncthreads();

        const int rowL = tid >> 1;          // 0..127
        const int par  = tid & 1;           // 0: m 0..4, 1: m 5..8
        const int row  = m0 + rowL;
        const bool live = row < B;
        const int rr = live ? row : 0;

        float x0[6];
        #pragma unroll
        for (int i = 0; i < 6; ++i)
            x0[i] = fmaf(__ldg(&x[(size_t)rr * 8 + i]), __ldg(&stdv[i]), __ldg(&mean[i]));

        const float px = x0[0], py = x0[1], theta = x0[2], v = x0[3];
        float st, ct;
        sincosf(theta, &st, &ct);

        const float p0  = __ldcg(&g_headAcc[(size_t)rr * 4 + 0]) + __ldg(&b31[0]);
        const float p1  = __ldcg(&g_headAcc[(size_t)rr * 4 + 1]) + __ldg(&b31[1]);
        const float pp1 = 4.0f / (1.0f + expf(-(__ldcg(&g_headAcc[(size_t)rr * 4 + 2]) + __ldg(&b32[0]))));
        const float pp2 = 4.0f / (1.0f + expf(-(__ldcg(&g_headAcc[(size_t)rr * 4 + 3]) + __ldg(&b32[1]))));

        const float twovv = 2.0f * v * v;
        const float psum  = pp1 + pp2;
        const float pprod = pp1 * pp2;

        float g1[5], g2[5], q[5];
        #pragma unroll
        for (int i = 0; i < 5; ++i) {
            const int m = par * 5 + i;
            if (m < 9) {
                float ox, oy, orad;
                if (m < 8) {
                    ox   = __ldg(&obstacles[m * 3]);
                    oy   = __ldg(&obstacles[m * 3 + 1]);
                    orad = __ldg(&obstacles[m * 3 + 2]);
                } else { ox = x0[4]; oy = x0[5]; orad = 0.5f; }
                const float dx = px - ox, dy = py - oy;
                const float R  = orad + 0.6f;
                const float barrier = dx * dx + dy * dy - R * R;
                const float proj = dx * ct + dy * st;
                const float bdot = 2.0f * v * proj;
                g1[i] = 2.0f * v * (dx * st - dy * ct);
                g2[i] = -2.0f * proj;
                const float hm = twovv + psum * bdot + pprod * barrier;
                q[i] = fmaf(g1[i], p0, fmaf(g2[i], p1, hm));
            } else {
                g1[i] = 0.f; g2[i] = 0.f; q[i] = 0.f;
            }
        }

        float a = 0.f, bq = 0.f, c = 0.f;
        #pragma unroll
        for (int i = 0; i < 5; ++i) {
            a  = fmaf(g1[i], g1[i], a);
            bq = fmaf(g2[i], g2[i], bq);
            c  = fmaf(g1[i], g2[i], c);
        }
        a  += __shfl_xor_sync(0xffffffffu, a,  1);
        bq += __shfl_xor_sync(0xffffffffu, bq, 1);
        c  += __shfl_xor_sync(0xffffffffu, c,  1);
        const float L = sqrtf(a * a + 2.0f * c * c + bq * bq) + 1e-6f;
        const float alpha = 1.0f / L;

        float lam[5];
        #pragma unroll
        for (int i = 0; i < 5; ++i) lam[i] = 0.0f;

        for (int it = 0; it < 300; ++it) {
            float t1p = ((g1[0] * lam[0] + g1[1] * lam[1]) +
                         (g1[2] * lam[2] + g1[3] * lam[3])) + g1[4] * lam[4];
            float t2p = ((g2[0] * lam[0] + g2[1] * lam[1]) +
                         (g2[2] * lam[2] + g2[3] * lam[3])) + g2[4] * lam[4];
            const float t1 = t1p + __shfl_xor_sync(0xffffffffu, t1p, 1);
            const float t2 = t2p + __shfl_xor_sync(0xffffffffu, t2p, 1);
            #pragma unroll
            for (int i = 0; i < 5; ++i) {
                const float grad = fmaf(g1[i], t1, fmaf(g2[i], t2, q[i]));
                lam[i] = fmaxf(fmaf(-alpha, grad, lam[i]), 0.0f);
            }
        }

        float t1p = 0.f, t2p = 0.f;
        #pragma unroll
        for (int i = 0; i < 5; ++i) {
            t1p = fmaf(g1[i], lam[i], t1p);
            t2p = fmaf(g2[i], lam[i], t2p);
        }
        const float t1 = t1p + __shfl_xor_sync(0xffffffffu, t1p, 1);
        const float t2 = t2p + __shfl_xor_sync(0xffffffffu, t2p, 1);
        if (par == 0 && live) {
            out[(size_t)row * 2 + 0] = -p0 - t1;
            out[(size_t)row * 2 + 1] = -p1 - t2;
        }
    }
}

// ---------------------------------------------------------------------------
extern "C" void kernel_launch(void* const* d_in, const int* in_sizes, int n_in,
                              void* d_out, int out_size)
{
    const float* x    = (const float*)d_in[0];
    const float* mean = (const float*)d_in[1];
    const float* stdv = (const float*)d_in[2];
    const float* W1   = (const float*)d_in[3];
    const float* b1   = (const float*)d_in[4];
    const float* W21  = (const float*)d_in[5];
    const float* b21  = (const float*)d_in[6];
    const float* W22  = (const float*)d_in[7];
    const float* b22  = (const float*)d_in[8];
    const float* W31  = (const float*)d_in[11];
    const float* b31  = (const float*)d_in[12];
    const float* W32  = (const float*)d_in[13];
    const float* b32  = (const float*)d_in[14];
    const float* obstacles = (const float*)d_in[17];
    float* out = (float*)d_out;

    int B = in_sizes[0] / 8;
    if (B > BMAX) B = BMAX;

    cudaFuncSetAttribute(gemm2_kernel,
                         cudaFuncAttributeMaxDynamicSharedMemorySize, SMEM_DYN);

    const int nb1 = (B + 15) / 16;
    prep_kernel<<<nb1 + 1024, 256>>>(x, W1, b1, W21, W22, B, nb1);

    const int mTiles = (B + 127) / 128;
    const int nGemm  = 8 * mTiles;
    gemm2_kernel<<<nGemm + mTiles, 256, SMEM_DYN>>>(
        b21, b22, W31, W32, x, mean, stdv, obstacles, b31, b32, out, B, nGemm);
}

// round 14
// speedup vs baseline: 1.1207x; 1.0011x over previous
#include <cuda_runtime.h>
#include <cuda_fp16.h>
#include <math.h>
#include <stdint.h>

// ===========================================================================
// BarrierNet on GB300 (generic compute_103 PTX -> legacy HMMA, rt~16/SMSP):
//   prep  : fused { h1=relu(x@W1+b1)->fp16 A (16 rows/blk, float4 x reads,
//                   direct W1 loads) ; [W21|W22]^T->fp16 B ; zero headAcc }
//   gemm2 : mma.sync fp16 GEMM, 128x128 CTA tile, 2 CTA/SM, 3-stage cp.async
//           (R10 config -- at the legacy-HMMA issue floor; fusion attempts
//           R11/R13 both regressed via register displacement)
//   qp    : rank-2 dual PGA, 2 lanes per row, 300 iters, alpha pre-folded
// ===========================================================================

#define BMAX 8192

__device__ __align__(16) __half g_A[(size_t)BMAX * 1024];
__device__ __align__(16) __half g_B[1024 * 1024];   // [n][k]
__device__ float g_headAcc[(size_t)BMAX * 4];

// ---------------------------------------------------------------------------
__device__ __forceinline__ uint32_t smem_u32(const void* p) {
    uint32_t a;
    asm("{ .reg .u64 t; cvta.to.shared.u64 t, %1; cvt.u32.u64 %0, t; }" : "=r"(a) : "l"(p));
    return a;
}
__device__ __forceinline__ void cpasync16(uint32_t s, const void* g) {
    asm volatile("cp.async.cg.shared.global [%0], [%1], 16;" :: "r"(s), "l"(g));
}
#define CP_COMMIT() asm volatile("cp.async.commit_group;" ::: "memory")
#define CP_WAIT1()  asm volatile("cp.async.wait_group 1;" ::: "memory")

__device__ __forceinline__ void ldsm_x4(uint32_t* r, uint32_t addr) {
    asm volatile("ldmatrix.sync.aligned.m8n8.x4.shared.b16 {%0,%1,%2,%3}, [%4];"
                 : "=r"(r[0]), "=r"(r[1]), "=r"(r[2]), "=r"(r[3]) : "r"(addr));
}
__device__ __forceinline__ void mma_f16(float* d, const uint32_t* a, const uint32_t* b) {
    asm volatile(
        "mma.sync.aligned.m16n8k16.row.col.f32.f16.f16.f32 "
        "{%0,%1,%2,%3}, {%4,%5,%6,%7}, {%8,%9}, {%0,%1,%2,%3};"
        : "+f"(d[0]), "+f"(d[1]), "+f"(d[2]), "+f"(d[3])
        : "r"(a[0]), "r"(a[1]), "r"(a[2]), "r"(a[3]), "r"(b[0]), "r"(b[1]));
}

// ---------------------------------------------------------------------------
// Kernel 1 (fused prep): blocks [0, nb1) gemm1 (16 rows each, direct W1 loads,
// float4 x reads); blocks [nb1, nb1+1024) wconv transpose+fp16.
// ---------------------------------------------------------------------------
__global__ __launch_bounds__(256)
void prep_kernel(const float* __restrict__ x,
                 const float* __restrict__ W1,
                 const float* __restrict__ b1,
                 const float* __restrict__ W21,
                 const float* __restrict__ W22,
                 int B, int nb1)
{
    __shared__ __align__(16) float sh[33 * 32 + 64];
    const int tid = threadIdx.x;

    if ((int)blockIdx.x < nb1) {
        // ---- gemm1: h1 = relu(x@W1+b1) -> fp16 A (16 rows per block) ----
        float* xs = sh;                      // [16][8]
        const int r0 = blockIdx.x * 16;

        if (tid < 128) xs[tid] = x[(size_t)r0 * 8 + tid];
        if (tid < 64)  g_headAcc[(size_t)r0 * 4 + tid] = 0.0f;

        const float2* __restrict__ W1v = (const float2*)W1;
        const float2* __restrict__ b1v = (const float2*)b1;
        float2 w01[8], w23[8];
        #pragma unroll
        for (int k = 0; k < 8; ++k) {
            w01[k] = W1v[k * 512 + tid];
            w23[k] = W1v[k * 512 + 256 + tid];
        }
        const float2 bb01 = b1v[tid];
        const float2 bb23 = b1v[256 + tid];
        __syncthreads();

        const int c0 = 2 * tid;
        const int c2 = 2 * tid + 512;
        #pragma unroll 4
        for (int r = 0; r < 16; ++r) {
            const float4 xr0 = *(const float4*)&xs[r * 8];
            const float4 xr1 = *(const float4*)&xs[r * 8 + 4];
            float xr[8] = { xr0.x, xr0.y, xr0.z, xr0.w, xr1.x, xr1.y, xr1.z, xr1.w };
            float a0 = bb01.x, a1 = bb01.y, a2 = bb23.x, a3 = bb23.y;
            #pragma unroll
            for (int k = 0; k < 8; ++k) {
                a0 = fmaf(xr[k], w01[k].x, a0);
                a1 = fmaf(xr[k], w01[k].y, a1);
                a2 = fmaf(xr[k], w23[k].x, a2);
                a3 = fmaf(xr[k], w23[k].y, a3);
            }
            __half2 h01 = __floats2half2_rn(fmaxf(a0, 0.f), fmaxf(a1, 0.f));
            __half2 h23 = __floats2half2_rn(fmaxf(a2, 0.f), fmaxf(a3, 0.f));
            *(__half2*)&g_A[(size_t)(r0 + r) * 1024 + c0] = h01;
            *(__half2*)&g_A[(size_t)(r0 + r) * 1024 + c2] = h23;
        }
    } else {
        // ---- wconv: [W21|W22]^T -> g_B[n][k] fp16 ----
        const int wc = blockIdx.x - nb1;          // 0..1023
        const int z  = wc >> 9;
        const int r  = wc & 511;
        const int n0 = (r & 15) * 32;
        const int k0 = (r >> 4) * 32;
        const int tx = tid & 31, ty = tid >> 5;
        float (*tile)[33] = (float (*)[33])sh;
        const float* W = z ? W22 : W21;

        #pragma unroll
        for (int i = ty; i < 32; i += 8)
            tile[i][tx] = W[(size_t)(k0 + i) * 512 + n0 + tx];
        __syncthreads();
        const int zb = z * 512;
        #pragma unroll
        for (int i = ty; i < 32; i += 8)
            g_B[(size_t)(zb + n0 + i) * 1024 + k0 + tx] = __float2half(tile[tx][i]);
    }
}

// ---------------------------------------------------------------------------
// Kernel 2: fp16 GEMM, 128(m) x 128(n) CTA tile, 2 CTA/SM, 3-stage pipeline.
// (R10 configuration -- measured at the legacy-HMMA issue floor.)
// ---------------------------------------------------------------------------
#define PITCHB   80u
#define OFF_A    0u
#define OFF_B    (128u * PITCHB)            // 10240
#define STAGE_BYTES (2u * 128u * PITCHB)    // 20480
#define SMEM_DYN (3u * STAGE_BYTES)         // 61440

__global__ __launch_bounds__(256, 2)
void gemm2_kernel(const float* __restrict__ b21, const float* __restrict__ b22,
                  const float* __restrict__ W31, const float* __restrict__ W32)
{
    extern __shared__ char smem[];
    __shared__ float sBias[128];
    __shared__ float sWh[256];

    const uint32_t sb = smem_u32(smem);
    const int tid  = threadIdx.x;
    const int lane = tid & 31;
    const int wid  = tid >> 5;
    const int wm   = wid & 1;
    const int wn   = wid >> 1;
    const int m0   = blockIdx.y * 128;
    const int n0   = blockIdx.x * 128;
    const int half = (n0 >= 512);
    const int nloc = n0 - half * 512;

    if (tid < 128) {
        const float* bp = half ? b22 : b21;
        const float* wp = half ? W32 : W31;
        sBias[tid]       = bp[nloc + tid];
        sWh[2 * tid]     = wp[(nloc + tid) * 2];
        sWh[2 * tid + 1] = wp[(nloc + tid) * 2 + 1];
    }

    const __half* __restrict__ srcA = g_A + (size_t)m0 * 1024;
    const __half* __restrict__ srcB = g_B + (size_t)n0 * 1024;

    const int lrow = tid >> 2;
    const int c8   = (tid & 3) * 8;
    const uint32_t cB = (uint32_t)(tid & 3) * 16u;

    const uint32_t aRC = (uint32_t)(wm * 64 + (lane & 15)) * PITCHB + (uint32_t)(lane >> 4) * 16u;
    const uint32_t bRC = (uint32_t)(wn * 32 + (lane & 7) + ((lane >> 4) << 3)) * PITCHB
                       + (uint32_t)((lane >> 3) & 1) * 16u;

    float acc[4][4][4];
    #pragma unroll
    for (int mb = 0; mb < 4; ++mb)
        #pragma unroll
        for (int nb = 0; nb < 4; ++nb)
            #pragma unroll
            for (int r = 0; r < 4; ++r) acc[mb][nb][r] = 0.0f;

    #define LOAD_STAGE(sbase, k0)                                                   \
    do {                                                                            \
        _Pragma("unroll")                                                           \
        for (int j = 0; j < 2; ++j) {                                               \
            const int r = lrow + j * 64;                                            \
            cpasync16((sbase) + OFF_A + (uint32_t)r * PITCHB + cB,                  \
                      srcA + (size_t)r * 1024 + (k0) + c8);                         \
            cpasync16((sbase) + OFF_B + (uint32_t)r * PITCHB + cB,                  \
                      srcB + (size_t)r * 1024 + (k0) + c8);                         \
        }                                                                           \
    } while (0)

    LOAD_STAGE(sb, 0);
    CP_COMMIT();
    LOAD_STAGE(sb + STAGE_BYTES, 32);
    CP_COMMIT();

    int cur = 0, nxt2 = 2;
    for (int t = 0; t < 32; ++t) {
        CP_WAIT1();
        __syncthreads();

        const uint32_t s = sb + (uint32_t)cur * STAGE_BYTES;
        #pragma unroll
        for (int ks = 0; ks < 2; ++ks) {
            const uint32_t kb = (uint32_t)ks * 32u;
            uint32_t bregs[4][2];
            #pragma unroll
            for (int nbp = 0; nbp < 2; ++nbp) {
                uint32_t r4[4];
                ldsm_x4(r4, s + OFF_B + bRC + (uint32_t)nbp * (16u * PITCHB) + kb);
                bregs[2 * nbp][0] = r4[0]; bregs[2 * nbp][1] = r4[1];
                bregs[2 * nbp + 1][0] = r4[2]; bregs[2 * nbp + 1][1] = r4[3];
            }
            #pragma unroll
            for (int mb = 0; mb < 4; ++mb) {
                uint32_t a4[4];
                ldsm_x4(a4, s + OFF_A + aRC + (uint32_t)mb * (16u * PITCHB) + kb);
                #pragma unroll
                for (int nb = 0; nb < 4; ++nb)
                    mma_f16(acc[mb][nb], a4, bregs[nb]);
            }
        }

        if (t + 2 < 32)
            LOAD_STAGE(sb + (uint32_t)nxt2 * STAGE_BYTES, (t + 2) * 32);
        CP_COMMIT();
        cur  = (cur  == 2) ? 0 : cur  + 1;
        nxt2 = (nxt2 == 2) ? 0 : nxt2 + 1;
    }

    // epilogue: bias+relu, head dots, quad reduce, atomicAdd
    const int colBase = wn * 32;
    #pragma unroll
    for (int mb = 0; mb < 4; ++mb) {
        #pragma unroll
        for (int h = 0; h < 2; ++h) {
            float s0 = 0.f, s1 = 0.f;
            #pragma unroll
            for (int nb = 0; nb < 4; ++nb) {
                const int c = colBase + nb * 8 + 2 * (lane & 3);
                const float v0 = fmaxf(acc[mb][nb][h * 2 + 0] + sBias[c],     0.f);
                const float v1 = fmaxf(acc[mb][nb][h * 2 + 1] + sBias[c + 1], 0.f);
                s0 = fmaf(v0, sWh[2 * c],     fmaf(v1, sWh[2 * (c + 1)],     s0));
                s1 = fmaf(v0, sWh[2 * c + 1], fmaf(v1, sWh[2 * (c + 1) + 1], s1));
            }
            s0 += __shfl_xor_sync(0xffffffffu, s0, 1);
            s0 += __shfl_xor_sync(0xffffffffu, s0, 2);
            s1 += __shfl_xor_sync(0xffffffffu, s1, 1);
            s1 += __shfl_xor_sync(0xffffffffu, s1, 2);
            if ((lane & 3) == 0) {
                const int row = m0 + wm * 64 + mb * 16 + h * 8 + (lane >> 2);
                float* dst = g_headAcc + (size_t)row * 4 + half * 2;
                atomicAdd(dst,     s0);
                atomicAdd(dst + 1, s1);
            }
        }
    }
}

// ---------------------------------------------------------------------------
// Kernel 3: QP, 2 lanes per row, 64-thread blocks, alpha pre-folded into
// G1/G2/Q so the update is lam = max(lam + fma(G1,t1, fma(G2,t2,Q)), 0).
// ---------------------------------------------------------------------------
__global__ __launch_bounds__(64)
void qp_kernel(const float* __restrict__ x,
               const float* __restrict__ mean,
               const float* __restrict__ stdv,
               const float* __restrict__ obstacles,
               const float* __restrict__ b31,
               const float* __restrict__ b32,
               float* __restrict__ out, int B)
{
    __shared__ float sObs[24];
    __shared__ float sMean[6], sStd[6], sB[4];
    const int tid = threadIdx.x;
    if (tid < 24) sObs[tid] = obstacles[tid];
    if (tid < 6) { sMean[tid] = mean[tid]; sStd[tid] = stdv[tid]; }
    if (tid < 2) { sB[tid] = b31[tid]; sB[2 + tid] = b32[tid]; }
    __syncthreads();

    const int gt   = blockIdx.x * 64 + tid;
    const int rowR = gt >> 1;
    const int par  = gt & 1;
    const int row  = rowR < B ? rowR : 0;

    float x0[6];
    #pragma unroll
    for (int i = 0; i < 6; ++i)
        x0[i] = fmaf(x[(size_t)row * 8 + i], sStd[i], sMean[i]);

    const float px = x0[0], py = x0[1], theta = x0[2], v = x0[3];
    float st, ct;
    sincosf(theta, &st, &ct);

    const float p0  = g_headAcc[(size_t)row * 4 + 0] + sB[0];
    const float p1  = g_headAcc[(size_t)row * 4 + 1] + sB[1];
    const float pp1 = 4.0f / (1.0f + expf(-(g_headAcc[(size_t)row * 4 + 2] + sB[2])));
    const float pp2 = 4.0f / (1.0f + expf(-(g_headAcc[(size_t)row * 4 + 3] + sB[3])));

    const float twovv = 2.0f * v * v;
    const float psum  = pp1 + pp2;
    const float pprod = pp1 * pp2;

    float g1[5], g2[5], q[5];
    #pragma unroll
    for (int i = 0; i < 5; ++i) {
        const int m = par * 5 + i;
        if (m < 9) {
            float ox, oy, orad;
            if (m < 8) { ox = sObs[m * 3]; oy = sObs[m * 3 + 1]; orad = sObs[m * 3 + 2]; }
            else       { ox = x0[4];       oy = x0[5];           orad = 0.5f; }
            const float dx = px - ox, dy = py - oy;
            const float R  = orad + 0.6f;
            const float barrier = dx * dx + dy * dy - R * R;
            const float proj = dx * ct + dy * st;
            const float bdot = 2.0f * v * proj;
            g1[i] = 2.0f * v * (dx * st - dy * ct);
            g2[i] = -2.0f * proj;
            const float hm = twovv + psum * bdot + pprod * barrier;
            q[i] = fmaf(g1[i], p0, fmaf(g2[i], p1, hm));
        } else {
            g1[i] = 0.f; g2[i] = 0.f; q[i] = 0.f;
        }
    }

    float a = 0.f, bq = 0.f, c = 0.f;
    #pragma unroll
    for (int i = 0; i < 5; ++i) {
        a  = fmaf(g1[i], g1[i], a);
        bq = fmaf(g2[i], g2[i], bq);
        c  = fmaf(g1[i], g2[i], c);
    }
    a  += __shfl_xor_sync(0xffffffffu, a,  1);
    bq += __shfl_xor_sync(0xffffffffu, bq, 1);
    c  += __shfl_xor_sync(0xffffffffu, c,  1);
    const float L = sqrtf(a * a + 2.0f * c * c + bq * bq) + 1e-6f;
    const float alpha = 1.0f / L;

    // pre-fold -alpha: update becomes lam = max(lam + G1*t1 + G2*t2 + Q, 0)
    float G1[5], G2[5], Q[5];
    #pragma unroll
    for (int i = 0; i < 5; ++i) {
        G1[i] = -alpha * g1[i];
        G2[i] = -alpha * g2[i];
        Q[i]  = -alpha * q[i];
    }

    float lam[5];
    #pragma unroll
    for (int i = 0; i < 5; ++i) lam[i] = 0.0f;

    for (int it = 0; it < 300; ++it) {
        float t1p = ((g1[0] * lam[0] + g1[1] * lam[1]) +
                     (g1[2] * lam[2] + g1[3] * lam[3])) + g1[4] * lam[4];
        float t2p = ((g2[0] * lam[0] + g2[1] * lam[1]) +
                     (g2[2] * lam[2] + g2[3] * lam[3])) + g2[4] * lam[4];
        const float t1 = t1p + __shfl_xor_sync(0xffffffffu, t1p, 1);
        const float t2 = t2p + __shfl_xor_sync(0xffffffffu, t2p, 1);
        #pragma unroll
        for (int i = 0; i < 5; ++i) {
            const float d = fmaf(G1[i], t1, fmaf(G2[i], t2, Q[i]));
            lam[i] = fmaxf(lam[i] + d, 0.0f);
        }
    }

    float t1p = 0.f, t2p = 0.f;
    #pragma unroll
    for (int i = 0; i < 5; ++i) {
        t1p = fmaf(g1[i], lam[i], t1p);
        t2p = fmaf(g2[i], lam[i], t2p);
    }
    const float t1 = t1p + __shfl_xor_sync(0xffffffffu, t1p, 1);
    const float t2 = t2p + __shfl_xor_sync(0xffffffffu, t2p, 1);
    if (par == 0 && rowR < B) {
        out[(size_t)rowR * 2 + 0] = -p0 - t1;
        out[(size_t)rowR * 2 + 1] = -p1 - t2;
    }
}

// ---------------------------------------------------------------------------
extern "C" void kernel_launch(void* const* d_in, const int* in_sizes, int n_in,
                              void* d_out, int out_size)
{
    const float* x    = (const float*)d_in[0];
    const float* mean = (const float*)d_in[1];
    const float* stdv = (const float*)d_in[2];
    const float* W1   = (const float*)d_in[3];
    const float* b1   = (const float*)d_in[4];
    const float* W21  = (const float*)d_in[5];
    const float* b21  = (const float*)d_in[6];
    const float* W22  = (const float*)d_in[7];
    const float* b22  = (const float*)d_in[8];
    const float* W31  = (const float*)d_in[11];
    const float* b31  = (const float*)d_in[12];
    const float* W32  = (const float*)d_in[13];
    const float* b32  = (const float*)d_in[14];
    const float* obstacles = (const float*)d_in[17];
    float* out = (float*)d_out;

    int B = in_sizes[0] / 8;
    if (B > BMAX) B = BMAX;

    cudaFuncSetAttribute(gemm2_kernel,
                         cudaFuncAttributeMaxDynamicSharedMemorySize, SMEM_DYN);

    const int nb1 = (B + 15) / 16;
    prep_kernel<<<nb1 + 1024, 256>>>(x, W1, b1, W21, W22, B, nb1);

    dim3 g2(8, (B + 127) / 128);
    gemm2_kernel<<<g2, 256, SMEM_DYN>>>(b21, b22, W31, W32);

    qp_kernel<<<(2 * B + 63) / 64, 64>>>(x, mean, stdv, obstacles, b31, b32, out, B);
}

// round 15
// speedup vs baseline: 1.1510x; 1.0270x over previous
#include <cuda_runtime.h>
#include <cuda_fp16.h>
#include <math.h>
#include <stdint.h>

// ===========================================================================
// BarrierNet on GB300 (generic compute_103 PTX -> legacy HMMA, rt~16/SMSP):
//   prep  : fused { h1=relu(x@W1+b1)->fp16 A (16 rows/blk, float4 x reads,
//                   direct W1 loads) ; [W21|W22]^T->fp16 B ; zero headAcc }
//   gemm2 : mma.sync fp16 GEMM, 128x128 CTA tile, 2 CTA/SM, 3-stage cp.async
//           -- measured at the HMMA issue floor (4.19M mma x rt16 / 592 SMSP)
//   qp    : rank-2 dual PGA, 2 lanes per row, 300 iters (R10 formulation)
// Best-measured component composition; converged configuration.
// ===========================================================================

#define BMAX 8192

__device__ __align__(16) __half g_A[(size_t)BMAX * 1024];
__device__ __align__(16) __half g_B[1024 * 1024];   // [n][k]
__device__ float g_headAcc[(size_t)BMAX * 4];

// ---------------------------------------------------------------------------
__device__ __forceinline__ uint32_t smem_u32(const void* p) {
    uint32_t a;
    asm("{ .reg .u64 t; cvta.to.shared.u64 t, %1; cvt.u32.u64 %0, t; }" : "=r"(a) : "l"(p));
    return a;
}
__device__ __forceinline__ void cpasync16(uint32_t s, const void* g) {
    asm volatile("cp.async.cg.shared.global [%0], [%1], 16;" :: "r"(s), "l"(g));
}
#define CP_COMMIT() asm volatile("cp.async.commit_group;" ::: "memory")
#define CP_WAIT1()  asm volatile("cp.async.wait_group 1;" ::: "memory")

__device__ __forceinline__ void ldsm_x4(uint32_t* r, uint32_t addr) {
    asm volatile("ldmatrix.sync.aligned.m8n8.x4.shared.b16 {%0,%1,%2,%3}, [%4];"
                 : "=r"(r[0]), "=r"(r[1]), "=r"(r[2]), "=r"(r[3]) : "r"(addr));
}
__device__ __forceinline__ void mma_f16(float* d, const uint32_t* a, const uint32_t* b) {
    asm volatile(
        "mma.sync.aligned.m16n8k16.row.col.f32.f16.f16.f32 "
        "{%0,%1,%2,%3}, {%4,%5,%6,%7}, {%8,%9}, {%0,%1,%2,%3};"
        : "+f"(d[0]), "+f"(d[1]), "+f"(d[2]), "+f"(d[3])
        : "r"(a[0]), "r"(a[1]), "r"(a[2]), "r"(a[3]), "r"(b[0]), "r"(b[1]));
}

// ---------------------------------------------------------------------------
// Kernel 1 (fused prep): blocks [0, nb1) gemm1 (16 rows each, direct W1 loads,
// float4 x reads); blocks [nb1, nb1+1024) wconv transpose+fp16.
// ---------------------------------------------------------------------------
__global__ __launch_bounds__(256)
void prep_kernel(const float* __restrict__ x,
                 const float* __restrict__ W1,
                 const float* __restrict__ b1,
                 const float* __restrict__ W21,
                 const float* __restrict__ W22,
                 int B, int nb1)
{
    __shared__ __align__(16) float sh[33 * 32 + 64];
    const int tid = threadIdx.x;

    if ((int)blockIdx.x < nb1) {
        // ---- gemm1: h1 = relu(x@W1+b1) -> fp16 A (16 rows per block) ----
        float* xs = sh;                      // [16][8]
        const int r0 = blockIdx.x * 16;

        if (tid < 128) xs[tid] = x[(size_t)r0 * 8 + tid];
        if (tid < 64)  g_headAcc[(size_t)r0 * 4 + tid] = 0.0f;

        const float2* __restrict__ W1v = (const float2*)W1;
        const float2* __restrict__ b1v = (const float2*)b1;
        float2 w01[8], w23[8];
        #pragma unroll
        for (int k = 0; k < 8; ++k) {
            w01[k] = W1v[k * 512 + tid];
            w23[k] = W1v[k * 512 + 256 + tid];
        }
        const float2 bb01 = b1v[tid];
        const float2 bb23 = b1v[256 + tid];
        __syncthreads();

        const int c0 = 2 * tid;
        const int c2 = 2 * tid + 512;
        #pragma unroll 4
        for (int r = 0; r < 16; ++r) {
            const float4 xr0 = *(const float4*)&xs[r * 8];
            const float4 xr1 = *(const float4*)&xs[r * 8 + 4];
            float xr[8] = { xr0.x, xr0.y, xr0.z, xr0.w, xr1.x, xr1.y, xr1.z, xr1.w };
            float a0 = bb01.x, a1 = bb01.y, a2 = bb23.x, a3 = bb23.y;
            #pragma unroll
            for (int k = 0; k < 8; ++k) {
                a0 = fmaf(xr[k], w01[k].x, a0);
                a1 = fmaf(xr[k], w01[k].y, a1);
                a2 = fmaf(xr[k], w23[k].x, a2);
                a3 = fmaf(xr[k], w23[k].y, a3);
            }
            __half2 h01 = __floats2half2_rn(fmaxf(a0, 0.f), fmaxf(a1, 0.f));
            __half2 h23 = __floats2half2_rn(fmaxf(a2, 0.f), fmaxf(a3, 0.f));
            *(__half2*)&g_A[(size_t)(r0 + r) * 1024 + c0] = h01;
            *(__half2*)&g_A[(size_t)(r0 + r) * 1024 + c2] = h23;
        }
    } else {
        // ---- wconv: [W21|W22]^T -> g_B[n][k] fp16 ----
        const int wc = blockIdx.x - nb1;          // 0..1023
        const int z  = wc >> 9;
        const int r  = wc & 511;
        const int n0 = (r & 15) * 32;
        const int k0 = (r >> 4) * 32;
        const int tx = tid & 31, ty = tid >> 5;
        float (*tile)[33] = (float (*)[33])sh;
        const float* W = z ? W22 : W21;

        #pragma unroll
        for (int i = ty; i < 32; i += 8)
            tile[i][tx] = W[(size_t)(k0 + i) * 512 + n0 + tx];
        __syncthreads();
        const int zb = z * 512;
        #pragma unroll
        for (int i = ty; i < 32; i += 8)
            g_B[(size_t)(zb + n0 + i) * 1024 + k0 + tx] = __float2half(tile[tx][i]);
    }
}

// ---------------------------------------------------------------------------
// Kernel 2: fp16 GEMM, 128(m) x 128(n) CTA tile, 2 CTA/SM, 3-stage pipeline.
// 8 warps = 2(m) x 4(n), warp tile 64x32. One __syncthreads per k32 stage.
// ---------------------------------------------------------------------------
#define PITCHB   80u
#define OFF_A    0u
#define OFF_B    (128u * PITCHB)            // 10240
#define STAGE_BYTES (2u * 128u * PITCHB)    // 20480
#define SMEM_DYN (3u * STAGE_BYTES)         // 61440

__global__ __launch_bounds__(256, 2)
void gemm2_kernel(const float* __restrict__ b21, const float* __restrict__ b22,
                  const float* __restrict__ W31, const float* __restrict__ W32)
{
    extern __shared__ char smem[];
    __shared__ float sBias[128];
    __shared__ float sWh[256];

    const uint32_t sb = smem_u32(smem);
    const int tid  = threadIdx.x;
    const int lane = tid & 31;
    const int wid  = tid >> 5;
    const int wm   = wid & 1;
    const int wn   = wid >> 1;
    const int m0   = blockIdx.y * 128;
    const int n0   = blockIdx.x * 128;
    const int half = (n0 >= 512);
    const int nloc = n0 - half * 512;

    if (tid < 128) {
        const float* bp = half ? b22 : b21;
        const float* wp = half ? W32 : W31;
        sBias[tid]       = bp[nloc + tid];
        sWh[2 * tid]     = wp[(nloc + tid) * 2];
        sWh[2 * tid + 1] = wp[(nloc + tid) * 2 + 1];
    }

    const __half* __restrict__ srcA = g_A + (size_t)m0 * 1024;
    const __half* __restrict__ srcB = g_B + (size_t)n0 * 1024;

    const int lrow = tid >> 2;
    const int c8   = (tid & 3) * 8;
    const uint32_t cB = (uint32_t)(tid & 3) * 16u;

    const uint32_t aRC = (uint32_t)(wm * 64 + (lane & 15)) * PITCHB + (uint32_t)(lane >> 4) * 16u;
    const uint32_t bRC = (uint32_t)(wn * 32 + (lane & 7) + ((lane >> 4) << 3)) * PITCHB
                       + (uint32_t)((lane >> 3) & 1) * 16u;

    float acc[4][4][4];
    #pragma unroll
    for (int mb = 0; mb < 4; ++mb)
        #pragma unroll
        for (int nb = 0; nb < 4; ++nb)
            #pragma unroll
            for (int r = 0; r < 4; ++r) acc[mb][nb][r] = 0.0f;

    #define LOAD_STAGE(sbase, k0)                                                   \
    do {                                                                            \
        _Pragma("unroll")                                                           \
        for (int j = 0; j < 2; ++j) {                                               \
            const int r = lrow + j * 64;                                            \
            cpasync16((sbase) + OFF_A + (uint32_t)r * PITCHB + cB,                  \
                      srcA + (size_t)r * 1024 + (k0) + c8);                         \
            cpasync16((sbase) + OFF_B + (uint32_t)r * PITCHB + cB,                  \
                      srcB + (size_t)r * 1024 + (k0) + c8);                         \
        }                                                                           \
    } while (0)

    LOAD_STAGE(sb, 0);
    CP_COMMIT();
    LOAD_STAGE(sb + STAGE_BYTES, 32);
    CP_COMMIT();

    int cur = 0, nxt2 = 2;
    for (int t = 0; t < 32; ++t) {
        CP_WAIT1();
        __syncthreads();

        const uint32_t s = sb + (uint32_t)cur * STAGE_BYTES;
        #pragma unroll
        for (int ks = 0; ks < 2; ++ks) {
            const uint32_t kb = (uint32_t)ks * 32u;
            uint32_t bregs[4][2];
            #pragma unroll
            for (int nbp = 0; nbp < 2; ++nbp) {
                uint32_t r4[4];
                ldsm_x4(r4, s + OFF_B + bRC + (uint32_t)nbp * (16u * PITCHB) + kb);
                bregs[2 * nbp][0] = r4[0]; bregs[2 * nbp][1] = r4[1];
                bregs[2 * nbp + 1][0] = r4[2]; bregs[2 * nbp + 1][1] = r4[3];
            }
            #pragma unroll
            for (int mb = 0; mb < 4; ++mb) {
                uint32_t a4[4];
                ldsm_x4(a4, s + OFF_A + aRC + (uint32_t)mb * (16u * PITCHB) + kb);
                #pragma unroll
                for (int nb = 0; nb < 4; ++nb)
                    mma_f16(acc[mb][nb], a4, bregs[nb]);
            }
        }

        if (t + 2 < 32)
            LOAD_STAGE(sb + (uint32_t)nxt2 * STAGE_BYTES, (t + 2) * 32);
        CP_COMMIT();
        cur  = (cur  == 2) ? 0 : cur  + 1;
        nxt2 = (nxt2 == 2) ? 0 : nxt2 + 1;
    }

    // epilogue: bias+relu, head dots, quad reduce, atomicAdd
    const int colBase = wn * 32;
    #pragma unroll
    for (int mb = 0; mb < 4; ++mb) {
        #pragma unroll
        for (int h = 0; h < 2; ++h) {
            float s0 = 0.f, s1 = 0.f;
            #pragma unroll
            for (int nb = 0; nb < 4; ++nb) {
                const int c = colBase + nb * 8 + 2 * (lane & 3);
                const float v0 = fmaxf(acc[mb][nb][h * 2 + 0] + sBias[c],     0.f);
                const float v1 = fmaxf(acc[mb][nb][h * 2 + 1] + sBias[c + 1], 0.f);
                s0 = fmaf(v0, sWh[2 * c],     fmaf(v1, sWh[2 * (c + 1)],     s0));
                s1 = fmaf(v0, sWh[2 * c + 1], fmaf(v1, sWh[2 * (c + 1) + 1], s1));
            }
            s0 += __shfl_xor_sync(0xffffffffu, s0, 1);
            s0 += __shfl_xor_sync(0xffffffffu, s0, 2);
            s1 += __shfl_xor_sync(0xffffffffu, s1, 1);
            s1 += __shfl_xor_sync(0xffffffffu, s1, 2);
            if ((lane & 3) == 0) {
                const int row = m0 + wm * 64 + mb * 16 + h * 8 + (lane >> 2);
                float* dst = g_headAcc + (size_t)row * 4 + half * 2;
                atomicAdd(dst,     s0);
                atomicAdd(dst + 1, s1);
            }
        }
    }
}

// ---------------------------------------------------------------------------
// Kernel 3: QP, 2 lanes per row, 64-thread blocks (R10 formulation).
// ---------------------------------------------------------------------------
__global__ __launch_bounds__(64)
void qp_kernel(const float* __restrict__ x,
               const float* __restrict__ mean,
               const float* __restrict__ stdv,
               const float* __restrict__ obstacles,
               const float* __restrict__ b31,
               const float* __restrict__ b32,
               float* __restrict__ out, int B)
{
    __shared__ float sObs[24];
    __shared__ float sMean[6], sStd[6], sB[4];
    const int tid = threadIdx.x;
    if (tid < 24) sObs[tid] = obstacles[tid];
    if (tid < 6) { sMean[tid] = mean[tid]; sStd[tid] = stdv[tid]; }
    if (tid < 2) { sB[tid] = b31[tid]; sB[2 + tid] = b32[tid]; }
    __syncthreads();

    const int gt   = blockIdx.x * 64 + tid;
    const int rowR = gt >> 1;
    const int par  = gt & 1;
    const int row  = rowR < B ? rowR : 0;

    float x0[6];
    #pragma unroll
    for (int i = 0; i < 6; ++i)
        x0[i] = fmaf(x[(size_t)row * 8 + i], sStd[i], sMean[i]);

    const float px = x0[0], py = x0[1], theta = x0[2], v = x0[3];
    float st, ct;
    sincosf(theta, &st, &ct);

    const float p0  = g_headAcc[(size_t)row * 4 + 0] + sB[0];
    const float p1  = g_headAcc[(size_t)row * 4 + 1] + sB[1];
    const float pp1 = 4.0f / (1.0f + expf(-(g_headAcc[(size_t)row * 4 + 2] + sB[2])));
    const float pp2 = 4.0f / (1.0f + expf(-(g_headAcc[(size_t)row * 4 + 3] + sB[3])));

    const float twovv = 2.0f * v * v;
    const float psum  = pp1 + pp2;
    const float pprod = pp1 * pp2;

    float g1[5], g2[5], q[5];
    #pragma unroll
    for (int i = 0; i < 5; ++i) {
        const int m = par * 5 + i;
        if (m < 9) {
            float ox, oy, orad;
            if (m < 8) { ox = sObs[m * 3]; oy = sObs[m * 3 + 1]; orad = sObs[m * 3 + 2]; }
            else       { ox = x0[4];       oy = x0[5];           orad = 0.5f; }
            const float dx = px - ox, dy = py - oy;
            const float R  = orad + 0.6f;
            const float barrier = dx * dx + dy * dy - R * R;
            const float proj = dx * ct + dy * st;
            const float bdot = 2.0f * v * proj;
            g1[i] = 2.0f * v * (dx * st - dy * ct);
            g2[i] = -2.0f * proj;
            const float hm = twovv + psum * bdot + pprod * barrier;
            q[i] = fmaf(g1[i], p0, fmaf(g2[i], p1, hm));
        } else {
            g1[i] = 0.f; g2[i] = 0.f; q[i] = 0.f;
        }
    }

    float a = 0.f, bq = 0.f, c = 0.f;
    #pragma unroll
    for (int i = 0; i < 5; ++i) {
        a  = fmaf(g1[i], g1[i], a);
        bq = fmaf(g2[i], g2[i], bq);
        c  = fmaf(g1[i], g2[i], c);
    }
    a  += __shfl_xor_sync(0xffffffffu, a,  1);
    bq += __shfl_xor_sync(0xffffffffu, bq, 1);
    c  += __shfl_xor_sync(0xffffffffu, c,  1);
    const float L = sqrtf(a * a + 2.0f * c * c + bq * bq) + 1e-6f;
    const float alpha = 1.0f / L;

    float lam[5];
    #pragma unroll
    for (int i = 0; i < 5; ++i) lam[i] = 0.0f;

    for (int it = 0; it < 300; ++it) {
        float t1p = ((g1[0] * lam[0] + g1[1] * lam[1]) +
                     (g1[2] * lam[2] + g1[3] * lam[3])) + g1[4] * lam[4];
        float t2p = ((g2[0] * lam[0] + g2[1] * lam[1]) +
                     (g2[2] * lam[2] + g2[3] * lam[3])) + g2[4] * lam[4];
        const float t1 = t1p + __shfl_xor_sync(0xffffffffu, t1p, 1);
        const float t2 = t2p + __shfl_xor_sync(0xffffffffu, t2p, 1);
        #pragma unroll
        for (int i = 0; i < 5; ++i) {
            const float grad = fmaf(g1[i], t1, fmaf(g2[i], t2, q[i]));
            lam[i] = fmaxf(fmaf(-alpha, grad, lam[i]), 0.0f);
        }
    }

    float t1p = 0.f, t2p = 0.f;
    #pragma unroll
    for (int i = 0; i < 5; ++i) {
        t1p = fmaf(g1[i], lam[i], t1p);
        t2p = fmaf(g2[i], lam[i], t2p);
    }
    const float t1 = t1p + __shfl_xor_sync(0xffffffffu, t1p, 1);
    const float t2 = t2p + __shfl_xor_sync(0xffffffffu, t2p, 1);
    if (par == 0 && rowR < B) {
        out[(size_t)rowR * 2 + 0] = -p0 - t1;
        out[(size_t)rowR * 2 + 1] = -p1 - t2;
    }
}

// ---------------------------------------------------------------------------
extern "C" void kernel_launch(void* const* d_in, const int* in_sizes, int n_in,
                              void* d_out, int out_size)
{
    const float* x    = (const float*)d_in[0];
    const float* mean = (const float*)d_in[1];
    const float* stdv = (const float*)d_in[2];
    const float* W1   = (const float*)d_in[3];
    const float* b1   = (const float*)d_in[4];
    const float* W21  = (const float*)d_in[5];
    const float* b21  = (const float*)d_in[6];
    const float* W22  = (const float*)d_in[7];
    const float* b22  = (const float*)d_in[8];
    const float* W31  = (const float*)d_in[11];
    const float* b31  = (const float*)d_in[12];
    const float* W32  = (const float*)d_in[13];
    const float* b32  = (const float*)d_in[14];
    const float* obstacles = (const float*)d_in[17];
    float* out = (float*)d_out;

    int B = in_sizes[0] / 8;
    if (B > BMAX) B = BMAX;

    cudaFuncSetAttribute(gemm2_kernel,
                         cudaFuncAttributeMaxDynamicSharedMemorySize, SMEM_DYN);

    const int nb1 = (B + 15) / 16;
    prep_kernel<<<nb1 + 1024, 256>>>(x, W1, b1, W21, W22, B, nb1);

    dim3 g2(8, (B + 127) / 128);
    gemm2_kernel<<<g2, 256, SMEM_DYN>>>(b21, b22, W31, W32);

    qp_kernel<<<(2 * B + 63) / 64, 64>>>(x, mean, stdv, obstacles, b31, b32, out, B);
}

// round 16
// speedup vs baseline: 1.1532x; 1.0019x over previous
#include <cuda_runtime.h>
#include <cuda_fp16.h>
#include <math.h>
#include <stdint.h>

// ===========================================================================
// BarrierNet on GB300 (generic compute_103 PTX -> legacy HMMA, rt~16/SMSP):
//   prep  : fused { h1=relu(x@W1+b1)->fp16 A (8 rows/blk, 1024 blocks,
//                   float4 x reads, direct W1 loads) ; [W21|W22]^T->fp16 B }
//   gemm2 : mma.sync fp16 GEMM, 128x128 CTA tile, 2 CTA/SM, 3-stage cp.async
//           -- measured at the HMMA issue floor (4.19M mma x rt16 / 592 SMSP)
//   qp    : rank-2 dual PGA, 2 lanes per row, 300 iters
// ===========================================================================

#define BMAX 8192

__device__ __align__(16) __half g_A[(size_t)BMAX * 1024];
__device__ __align__(16) __half g_B[1024 * 1024];   // [n][k]
__device__ float g_headAcc[(size_t)BMAX * 4];

// ---------------------------------------------------------------------------
__device__ __forceinline__ uint32_t smem_u32(const void* p) {
    uint32_t a;
    asm("{ .reg .u64 t; cvta.to.shared.u64 t, %1; cvt.u32.u64 %0, t; }" : "=r"(a) : "l"(p));
    return a;
}
__device__ __forceinline__ void cpasync16(uint32_t s, const void* g) {
    asm volatile("cp.async.cg.shared.global [%0], [%1], 16;" :: "r"(s), "l"(g));
}
#define CP_COMMIT() asm volatile("cp.async.commit_group;" ::: "memory")
#define CP_WAIT1()  asm volatile("cp.async.wait_group 1;" ::: "memory")

__device__ __forceinline__ void ldsm_x4(uint32_t* r, uint32_t addr) {
    asm volatile("ldmatrix.sync.aligned.m8n8.x4.shared.b16 {%0,%1,%2,%3}, [%4];"
                 : "=r"(r[0]), "=r"(r[1]), "=r"(r[2]), "=r"(r[3]) : "r"(addr));
}
__device__ __forceinline__ void mma_f16(float* d, const uint32_t* a, const uint32_t* b) {
    asm volatile(
        "mma.sync.aligned.m16n8k16.row.col.f32.f16.f16.f32 "
        "{%0,%1,%2,%3}, {%4,%5,%6,%7}, {%8,%9}, {%0,%1,%2,%3};"
        : "+f"(d[0]), "+f"(d[1]), "+f"(d[2]), "+f"(d[3])
        : "r"(a[0]), "r"(a[1]), "r"(a[2]), "r"(a[3]), "r"(b[0]), "r"(b[1]));
}

// ---------------------------------------------------------------------------
// Kernel 1 (fused prep): blocks [0, nb1) gemm1 (8 rows each, direct W1 loads,
// float4 x reads); blocks [nb1, nb1+1024) wconv transpose+fp16.
// ---------------------------------------------------------------------------
__global__ __launch_bounds__(256)
void prep_kernel(const float* __restrict__ x,
                 const float* __restrict__ W1,
                 const float* __restrict__ b1,
                 const float* __restrict__ W21,
                 const float* __restrict__ W22,
                 int B, int nb1)
{
    __shared__ __align__(16) float sh[33 * 32 + 64];
    const int tid = threadIdx.x;

    if ((int)blockIdx.x < nb1) {
        // ---- gemm1: h1 = relu(x@W1+b1) -> fp16 A (8 rows per block) ----
        float* xs = sh;                      // [8][8]
        const int r0 = blockIdx.x * 8;

        if (tid < 64) xs[tid] = x[(size_t)r0 * 8 + tid];
        if (tid < 32) g_headAcc[(size_t)r0 * 4 + tid] = 0.0f;

        const float2* __restrict__ W1v = (const float2*)W1;
        const float2* __restrict__ b1v = (const float2*)b1;
        float2 w01[8], w23[8];
        #pragma unroll
        for (int k = 0; k < 8; ++k) {
            w01[k] = W1v[k * 512 + tid];
            w23[k] = W1v[k * 512 + 256 + tid];
        }
        const float2 bb01 = b1v[tid];
        const float2 bb23 = b1v[256 + tid];
        __syncthreads();

        const int c0 = 2 * tid;
        const int c2 = 2 * tid + 512;
        #pragma unroll
        for (int r = 0; r < 8; ++r) {
            const float4 xr0 = *(const float4*)&xs[r * 8];
            const float4 xr1 = *(const float4*)&xs[r * 8 + 4];
            float xr[8] = { xr0.x, xr0.y, xr0.z, xr0.w, xr1.x, xr1.y, xr1.z, xr1.w };
            float a0 = bb01.x, a1 = bb01.y, a2 = bb23.x, a3 = bb23.y;
            #pragma unroll
            for (int k = 0; k < 8; ++k) {
                a0 = fmaf(xr[k], w01[k].x, a0);
                a1 = fmaf(xr[k], w01[k].y, a1);
                a2 = fmaf(xr[k], w23[k].x, a2);
                a3 = fmaf(xr[k], w23[k].y, a3);
            }
            __half2 h01 = __floats2half2_rn(fmaxf(a0, 0.f), fmaxf(a1, 0.f));
            __half2 h23 = __floats2half2_rn(fmaxf(a2, 0.f), fmaxf(a3, 0.f));
            *(__half2*)&g_A[(size_t)(r0 + r) * 1024 + c0] = h01;
            *(__half2*)&g_A[(size_t)(r0 + r) * 1024 + c2] = h23;
        }
    } else {
        // ---- wconv: [W21|W22]^T -> g_B[n][k] fp16 ----
        const int wc = blockIdx.x - nb1;          // 0..1023
        const int z  = wc >> 9;
        const int r  = wc & 511;
        const int n0 = (r & 15) * 32;
        const int k0 = (r >> 4) * 32;
        const int tx = tid & 31, ty = tid >> 5;
        float (*tile)[33] = (float (*)[33])sh;
        const float* W = z ? W22 : W21;

        #pragma unroll
        for (int i = ty; i < 32; i += 8)
            tile[i][tx] = W[(size_t)(k0 + i) * 512 + n0 + tx];
        __syncthreads();
        const int zb = z * 512;
        #pragma unroll
        for (int i = ty; i < 32; i += 8)
            g_B[(size_t)(zb + n0 + i) * 1024 + k0 + tx] = __float2half(tile[tx][i]);
    }
}

// ---------------------------------------------------------------------------
// Kernel 2: fp16 GEMM, 128(m) x 128(n) CTA tile, 2 CTA/SM, 3-stage pipeline.
// 8 warps = 2(m) x 4(n), warp tile 64x32. One __syncthreads per k32 stage.
// ---------------------------------------------------------------------------
#define PITCHB   80u
#define OFF_A    0u
#define OFF_B    (128u * PITCHB)            // 10240
#define STAGE_BYTES (2u * 128u * PITCHB)    // 20480
#define SMEM_DYN (3u * STAGE_BYTES)         // 61440

__global__ __launch_bounds__(256, 2)
void gemm2_kernel(const float* __restrict__ b21, const float* __restrict__ b22,
                  const float* __restrict__ W31, const float* __restrict__ W32)
{
    extern __shared__ char smem[];
    __shared__ float sBias[128];
    __shared__ float sWh[256];

    const uint32_t sb = smem_u32(smem);
    const int tid  = threadIdx.x;
    const int lane = tid & 31;
    const int wid  = tid >> 5;
    const int wm   = wid & 1;
    const int wn   = wid >> 1;
    const int m0   = blockIdx.y * 128;
    const int n0   = blockIdx.x * 128;
    const int half = (n0 >= 512);
    const int nloc = n0 - half * 512;

    if (tid < 128) {
        const float* bp = half ? b22 : b21;
        const float* wp = half ? W32 : W31;
        sBias[tid]       = bp[nloc + tid];
        sWh[2 * tid]     = wp[(nloc + tid) * 2];
        sWh[2 * tid + 1] = wp[(nloc + tid) * 2 + 1];
    }

    const __half* __restrict__ srcA = g_A + (size_t)m0 * 1024;
    const __half* __restrict__ srcB = g_B + (size_t)n0 * 1024;

    const int lrow = tid >> 2;
    const int c8   = (tid & 3) * 8;
    const uint32_t cB = (uint32_t)(tid & 3) * 16u;

    const uint32_t aRC = (uint32_t)(wm * 64 + (lane & 15)) * PITCHB + (uint32_t)(lane >> 4) * 16u;
    const uint32_t bRC = (uint32_t)(wn * 32 + (lane & 7) + ((lane >> 4) << 3)) * PITCHB
                       + (uint32_t)((lane >> 3) & 1) * 16u;

    float acc[4][4][4];
    #pragma unroll
    for (int mb = 0; mb < 4; ++mb)
        #pragma unroll
        for (int nb = 0; nb < 4; ++nb)
            #pragma unroll
            for (int r = 0; r < 4; ++r) acc[mb][nb][r] = 0.0f;

    #define LOAD_STAGE(sbase, k0)                                                   \
    do {                                                                            \
        _Pragma("unroll")                                                           \
        for (int j = 0; j < 2; ++j) {                                               \
            const int r = lrow + j * 64;                                            \
            cpasync16((sbase) + OFF_A + (uint32_t)r * PITCHB + cB,                  \
                      srcA + (size_t)r * 1024 + (k0) + c8);                         \
            cpasync16((sbase) + OFF_B + (uint32_t)r * PITCHB + cB,                  \
                      srcB + (size_t)r * 1024 + (k0) + c8);                         \
        }                                                                           \
    } while (0)

    LOAD_STAGE(sb, 0);
    CP_COMMIT();
    LOAD_STAGE(sb + STAGE_BYTES, 32);
    CP_COMMIT();

    int cur = 0, nxt2 = 2;
    for (int t = 0; t < 32; ++t) {
        CP_WAIT1();
        __syncthreads();

        const uint32_t s = sb + (uint32_t)cur * STAGE_BYTES;
        #pragma unroll
        for (int ks = 0; ks < 2; ++ks) {
            const uint32_t kb = (uint32_t)ks * 32u;
            uint32_t bregs[4][2];
            #pragma unroll
            for (int nbp = 0; nbp < 2; ++nbp) {
                uint32_t r4[4];
                ldsm_x4(r4, s + OFF_B + bRC + (uint32_t)nbp * (16u * PITCHB) + kb);
                bregs[2 * nbp][0] = r4[0]; bregs[2 * nbp][1] = r4[1];
                bregs[2 * nbp + 1][0] = r4[2]; bregs[2 * nbp + 1][1] = r4[3];
            }
            #pragma unroll
            for (int mb = 0; mb < 4; ++mb) {
                uint32_t a4[4];
                ldsm_x4(a4, s + OFF_A + aRC + (uint32_t)mb * (16u * PITCHB) + kb);
                #pragma unroll
                for (int nb = 0; nb < 4; ++nb)
                    mma_f16(acc[mb][nb], a4, bregs[nb]);
            }
        }

        if (t + 2 < 32)
            LOAD_STAGE(sb + (uint32_t)nxt2 * STAGE_BYTES, (t + 2) * 32);
        CP_COMMIT();
        cur  = (cur  == 2) ? 0 : cur  + 1;
        nxt2 = (nxt2 == 2) ? 0 : nxt2 + 1;
    }

    // epilogue: bias+relu, head dots, quad reduce, atomicAdd
    const int colBase = wn * 32;
    #pragma unroll
    for (int mb = 0; mb < 4; ++mb) {
        #pragma unroll
        for (int h = 0; h < 2; ++h) {
            float s0 = 0.f, s1 = 0.f;
            #pragma unroll
            for (int nb = 0; nb < 4; ++nb) {
                const int c = colBase + nb * 8 + 2 * (lane & 3);
                const float v0 = fmaxf(acc[mb][nb][h * 2 + 0] + sBias[c],     0.f);
                const float v1 = fmaxf(acc[mb][nb][h * 2 + 1] + sBias[c + 1], 0.f);
                s0 = fmaf(v0, sWh[2 * c],     fmaf(v1, sWh[2 * (c + 1)],     s0));
                s1 = fmaf(v0, sWh[2 * c + 1], fmaf(v1, sWh[2 * (c + 1) + 1], s1));
            }
            s0 += __shfl_xor_sync(0xffffffffu, s0, 1);
            s0 += __shfl_xor_sync(0xffffffffu, s0, 2);
            s1 += __shfl_xor_sync(0xffffffffu, s1, 1);
            s1 += __shfl_xor_sync(0xffffffffu, s1, 2);
            if ((lane & 3) == 0) {
                const int row = m0 + wm * 64 + mb * 16 + h * 8 + (lane >> 2);
                float* dst = g_headAcc + (size_t)row * 4 + half * 2;
                atomicAdd(dst,     s0);
                atomicAdd(dst + 1, s1);
            }
        }
    }
}

// ---------------------------------------------------------------------------
// Kernel 3: QP, 2 lanes per row, 64-thread blocks.
// ---------------------------------------------------------------------------
__global__ __launch_bounds__(64)
void qp_kernel(const float* __restrict__ x,
               const float* __restrict__ mean,
               const float* __restrict__ stdv,
               const float* __restrict__ obstacles,
               const float* __restrict__ b31,
               const float* __restrict__ b32,
               float* __restrict__ out, int B)
{
    __shared__ float sObs[24];
    __shared__ float sMean[6], sStd[6], sB[4];
    const int tid = threadIdx.x;
    if (tid < 24) sObs[tid] = obstacles[tid];
    if (tid < 6) { sMean[tid] = mean[tid]; sStd[tid] = stdv[tid]; }
    if (tid < 2) { sB[tid] = b31[tid]; sB[2 + tid] = b32[tid]; }
    __syncthreads();

    const int gt   = blockIdx.x * 64 + tid;
    const int rowR = gt >> 1;
    const int par  = gt & 1;
    const int row  = rowR < B ? rowR : 0;

    float x0[6];
    #pragma unroll
    for (int i = 0; i < 6; ++i)
        x0[i] = fmaf(x[(size_t)row * 8 + i], sStd[i], sMean[i]);

    const float px = x0[0], py = x0[1], theta = x0[2], v = x0[3];
    float st, ct;
    sincosf(theta, &st, &ct);

    const float p0  = g_headAcc[(size_t)row * 4 + 0] + sB[0];
    const float p1  = g_headAcc[(size_t)row * 4 + 1] + sB[1];
    const float pp1 = 4.0f / (1.0f + expf(-(g_headAcc[(size_t)row * 4 + 2] + sB[2])));
    const float pp2 = 4.0f / (1.0f + expf(-(g_headAcc[(size_t)row * 4 + 3] + sB[3])));

    const float twovv = 2.0f * v * v;
    const float psum  = pp1 + pp2;
    const float pprod = pp1 * pp2;

    float g1[5], g2[5], q[5];
    #pragma unroll
    for (int i = 0; i < 5; ++i) {
        const int m = par * 5 + i;
        if (m < 9) {
            float ox, oy, orad;
            if (m < 8) { ox = sObs[m * 3]; oy = sObs[m * 3 + 1]; orad = sObs[m * 3 + 2]; }
            else       { ox = x0[4];       oy = x0[5];           orad = 0.5f; }
            const float dx = px - ox, dy = py - oy;
            const float R  = orad + 0.6f;
            const float barrier = dx * dx + dy * dy - R * R;
            const float proj = dx * ct + dy * st;
            const float bdot = 2.0f * v * proj;
            g1[i] = 2.0f * v * (dx * st - dy * ct);
            g2[i] = -2.0f * proj;
            const float hm = twovv + psum * bdot + pprod * barrier;
            q[i] = fmaf(g1[i], p0, fmaf(g2[i], p1, hm));
        } else {
            g1[i] = 0.f; g2[i] = 0.f; q[i] = 0.f;
        }
    }

    float a = 0.f, bq = 0.f, c = 0.f;
    #pragma unroll
    for (int i = 0; i < 5; ++i) {
        a  = fmaf(g1[i], g1[i], a);
        bq = fmaf(g2[i], g2[i], bq);
        c  = fmaf(g1[i], g2[i], c);
    }
    a  += __shfl_xor_sync(0xffffffffu, a,  1);
    bq += __shfl_xor_sync(0xffffffffu, bq, 1);
    c  += __shfl_xor_sync(0xffffffffu, c,  1);
    const float L = sqrtf(a * a + 2.0f * c * c + bq * bq) + 1e-6f;
    const float alpha = 1.0f / L;

    float lam[5];
    #pragma unroll
    for (int i = 0; i < 5; ++i) lam[i] = 0.0f;

    for (int it = 0; it < 300; ++it) {
        float t1p = ((g1[0] * lam[0] + g1[1] * lam[1]) +
                     (g1[2] * lam[2] + g1[3] * lam[3])) + g1[4] * lam[4];
        float t2p = ((g2[0] * lam[0] + g2[1] * lam[1]) +
                     (g2[2] * lam[2] + g2[3] * lam[3])) + g2[4] * lam[4];
        const float t1 = t1p + __shfl_xor_sync(0xffffffffu, t1p, 1);
        const float t2 = t2p + __shfl_xor_sync(0xffffffffu, t2p, 1);
        #pragma unroll
        for (int i = 0; i < 5; ++i) {
            const float grad = fmaf(g1[i], t1, fmaf(g2[i], t2, q[i]));
            lam[i] = fmaxf(fmaf(-alpha, grad, lam[i]), 0.0f);
        }
    }

    float t1p = 0.f, t2p = 0.f;
    #pragma unroll
    for (int i = 0; i < 5; ++i) {
        t1p = fmaf(g1[i], lam[i], t1p);
        t2p = fmaf(g2[i], lam[i], t2p);
    }
    const float t1 = t1p + __shfl_xor_sync(0xffffffffu, t1p, 1);
    const float t2 = t2p + __shfl_xor_sync(0xffffffffu, t2p, 1);
    if (par == 0 && rowR < B) {
        out[(size_t)rowR * 2 + 0] = -p0 - t1;
        out[(size_t)rowR * 2 + 1] = -p1 - t2;
    }
}

// ---------------------------------------------------------------------------
extern "C" void kernel_launch(void* const* d_in, const int* in_sizes, int n_in,
                              void* d_out, int out_size)
{
    const float* x    = (const float*)d_in[0];
    const float* mean = (const float*)d_in[1];
    const float* stdv = (const float*)d_in[2];
    const float* W1   = (const float*)d_in[3];
    const float* b1   = (const float*)d_in[4];
    const float* W21  = (const float*)d_in[5];
    const float* b21  = (const float*)d_in[6];
    const float* W22  = (const float*)d_in[7];
    const float* b22  = (const float*)d_in[8];
    const float* W31  = (const float*)d_in[11];
    const float* b31  = (const float*)d_in[12];
    const float* W32  = (const float*)d_in[13];
    const float* b32  = (const float*)d_in[14];
    const float* obstacles = (const float*)d_in[17];
    float* out = (float*)d_out;

    int B = in_sizes[0] / 8;
    if (B > BMAX) B = BMAX;

    cudaFuncSetAttribute(gemm2_kernel,
                         cudaFuncAttributeMaxDynamicSharedMemorySize, SMEM_DYN);

    const int nb1 = (B + 7) / 8;
    prep_kernel<<<nb1 + 1024, 256>>>(x, W1, b1, W21, W22, B, nb1);

    dim3 g2(8, (B + 127) / 128);
    gemm2_kernel<<<g2, 256, SMEM_DYN>>>(b21, b22, W31, W32);

    qp_kernel<<<(2 * B + 63) / 64, 64>>>(x, mean, stdv, obstacles, b31, b32, out, B);
}